// round 1
// baseline (speedup 1.0000x reference)
#include <cuda_runtime.h>
#include <cstdint>

#define DIM   4096
#define N_OBJ 256
#define N_REL 1024
#define EPSF  1e-7f

// ---------------- scratch (static device arrays; no allocation) ----------------
// h_pred[z]: z=0 -> relu(x_pred@W0^T+b0), z=1 -> W1, z=2 -> W5
__device__ float g_h_pred[3][N_REL * DIM];
// h_obj[z]:  z=0 -> relu(x_obj@W4^T+b4), z=1 -> W2, z=2 -> W3
__device__ float g_h_obj[3][N_OBJ * DIM];
__device__ float g_colsum4[DIM];

// ---------------- fused GEMM: H = relu(X @ W^T + b) ----------------
// A: X [M x K] row-major. B: W [N x K] row-major (so NT gemm). C: H [M x N].
// Tiles: BM=BN=128, BK=32. 256 threads, 8x8 per-thread micro-tile.
// z-batched: 3 weight matrices per launch (mode selects obj/pred mapping).
__global__ __launch_bounds__(256, 2)
void gemm_relu_nt(const float* __restrict__ X,
                  const float* __restrict__ W_all,
                  const float* __restrict__ b_all,
                  int M, int mode /*0=pred,1=obj*/)
{
    const int z = blockIdx.z;
    // pred launch: z -> W {0,1,5}; obj launch: z -> W {4,2,3}
    const int widx = mode ? ((z == 0) ? 4 : (z + 1)) : ((z == 2) ? 5 : z);
    const float* __restrict__ W    = W_all + (size_t)widx * DIM * DIM;
    const float* __restrict__ bias = b_all + (size_t)widx * DIM;
    float* __restrict__ H = mode ? &g_h_obj[z][0] : &g_h_pred[z][0];

    __shared__ float As[32][128];  // transposed: As[k][m]
    __shared__ float Bs[32][128];  // transposed: Bs[k][n]

    const int tid = threadIdx.x;
    const int bm = blockIdx.y * 128;
    const int bn = blockIdx.x * 128;
    const int ty = tid >> 4;     // 0..15
    const int tx = tid & 15;     // 0..15

    float acc[8][8];
#pragma unroll
    for (int i = 0; i < 8; i++)
#pragma unroll
        for (int j = 0; j < 8; j++) acc[i][j] = 0.f;

    for (int k0 = 0; k0 < DIM; k0 += 32) {
#pragma unroll
        for (int i = 0; i < 4; i++) {
            int p   = i * 256 + tid;   // float4 index 0..1023
            int row = p >> 3;          // 0..127
            int kv  = (p & 7) * 4;     // 0,4,...,28
            float4 va = *reinterpret_cast<const float4*>(
                &X[(size_t)(bm + row) * DIM + k0 + kv]);
            As[kv + 0][row] = va.x; As[kv + 1][row] = va.y;
            As[kv + 2][row] = va.z; As[kv + 3][row] = va.w;
            float4 vb = *reinterpret_cast<const float4*>(
                &W[(size_t)(bn + row) * DIM + k0 + kv]);
            Bs[kv + 0][row] = vb.x; Bs[kv + 1][row] = vb.y;
            Bs[kv + 2][row] = vb.z; Bs[kv + 3][row] = vb.w;
        }
        __syncthreads();

#pragma unroll
        for (int kk = 0; kk < 32; kk++) {
            float a[8], b[8];
            *reinterpret_cast<float4*>(&a[0]) =
                *reinterpret_cast<const float4*>(&As[kk][ty * 4]);
            *reinterpret_cast<float4*>(&a[4]) =
                *reinterpret_cast<const float4*>(&As[kk][64 + ty * 4]);
            *reinterpret_cast<float4*>(&b[0]) =
                *reinterpret_cast<const float4*>(&Bs[kk][tx * 4]);
            *reinterpret_cast<float4*>(&b[4]) =
                *reinterpret_cast<const float4*>(&Bs[kk][64 + tx * 4]);
#pragma unroll
            for (int i = 0; i < 8; i++)
#pragma unroll
                for (int j = 0; j < 8; j++) acc[i][j] += a[i] * b[j];
        }
        __syncthreads();
    }

    // epilogue: bias + relu, vectorized stores
    float bb[8];
#pragma unroll
    for (int j = 0; j < 4; j++) {
        bb[j]     = bias[bn + tx * 4 + j];
        bb[4 + j] = bias[bn + 64 + tx * 4 + j];
    }
#pragma unroll
    for (int i = 0; i < 8; i++) {
        int row = bm + ((i < 4) ? (ty * 4 + i) : (64 + ty * 4 + i - 4));
        float* Hrow = H + (size_t)row * DIM;
#pragma unroll
        for (int jh = 0; jh < 2; jh++) {
            int col = bn + (jh ? (64 + tx * 4) : (tx * 4));
            float4 r;
            r.x = fmaxf(acc[i][jh * 4 + 0] + bb[jh * 4 + 0], 0.f);
            r.y = fmaxf(acc[i][jh * 4 + 1] + bb[jh * 4 + 1], 0.f);
            r.z = fmaxf(acc[i][jh * 4 + 2] + bb[jh * 4 + 2], 0.f);
            r.w = fmaxf(acc[i][jh * 4 + 3] + bb[jh * 4 + 3], 0.f);
            *reinterpret_cast<float4*>(Hrow + col) = r;
        }
    }
}

// ---------------- column sums of h4 (g_h_obj[0]) ----------------
__global__ void colsum4_kernel()
{
    int c = blockIdx.x * blockDim.x + threadIdx.x;  // 0..4095
    float s = 0.f;
    for (int r = 0; r < N_OBJ; r++) s += g_h_obj[0][(size_t)r * DIM + c];
    g_colsum4[c] = s;
}

// ---------------- obj side: aggregate + final x_obj ----------------
// x_obj_out[i] = obj_feats[i] + (s_obj + s_rel_sub + s_rel_obj)/3
// s_obj      = (colsum4 - h4[i]) / (255+eps)
// s_rel_sub  = sum_{r: subj(r)=i} h0[r] / (cnt+eps)
// s_rel_obj  = sum_{r: obj(r)=i}  h1[r] / (cnt+eps)
__global__ __launch_bounds__(256)
void obj_final_kernel(const float* __restrict__ obj_feats,
                      const int*   __restrict__ rel_inds,
                      float* __restrict__ out_obj)
{
    __shared__ int s_sub[N_REL];
    __shared__ int s_obv[N_REL];
    const int tid = threadIdx.x;
    for (int t = tid; t < N_REL; t += 256) {
        s_sub[t] = rel_inds[2 * t + 0];
        s_obv[t] = rel_inds[2 * t + 1];
    }
    __syncthreads();

    const int i = blockIdx.x;
    float4 sum0[4], sum1[4];
#pragma unroll
    for (int q = 0; q < 4; q++) {
        sum0[q] = make_float4(0.f, 0.f, 0.f, 0.f);
        sum1[q] = make_float4(0.f, 0.f, 0.f, 0.f);
    }
    int c0 = 0, c1 = 0;

    for (int r = 0; r < N_REL; r++) {
        if (s_sub[r] == i) {
            c0++;
            const float* row = &g_h_pred[0][(size_t)r * DIM];
#pragma unroll
            for (int q = 0; q < 4; q++) {
                float4 v = *reinterpret_cast<const float4*>(row + q * 1024 + tid * 4);
                sum0[q].x += v.x; sum0[q].y += v.y; sum0[q].z += v.z; sum0[q].w += v.w;
            }
        }
        if (s_obv[r] == i) {
            c1++;
            const float* row = &g_h_pred[1][(size_t)r * DIM];
#pragma unroll
            for (int q = 0; q < 4; q++) {
                float4 v = *reinterpret_cast<const float4*>(row + q * 1024 + tid * 4);
                sum1[q].x += v.x; sum1[q].y += v.y; sum1[q].z += v.z; sum1[q].w += v.w;
            }
        }
    }

    const float inv0 = 1.f / ((float)c0 + EPSF);
    const float inv1 = 1.f / ((float)c1 + EPSF);
    const float invo = 1.f / (255.f + EPSF);
    const float third = 1.f / 3.f;

#pragma unroll
    for (int q = 0; q < 4; q++) {
        int col = q * 1024 + tid * 4;
        float4 h4v = *reinterpret_cast<const float4*>(&g_h_obj[0][(size_t)i * DIM + col]);
        float4 cs  = *reinterpret_cast<const float4*>(&g_colsum4[col]);
        float4 bs  = *reinterpret_cast<const float4*>(&obj_feats[(size_t)i * DIM + col]);
        float4 o;
        o.x = bs.x + ((cs.x - h4v.x) * invo + sum0[q].x * inv0 + sum1[q].x * inv1) * third;
        o.y = bs.y + ((cs.y - h4v.y) * invo + sum0[q].y * inv0 + sum1[q].y * inv1) * third;
        o.z = bs.z + ((cs.z - h4v.z) * invo + sum0[q].z * inv0 + sum1[q].z * inv1) * third;
        o.w = bs.w + ((cs.w - h4v.w) * invo + sum0[q].w * inv0 + sum1[q].w * inv1) * third;
        *reinterpret_cast<float4*>(&out_obj[(size_t)i * DIM + col]) = o;
    }
}

// ---------------- pred side: adjacency aggregate + gathers + final x_pred ----------------
// x_pred_out[r] = pred_feats[r] + ( h2[subj(r)]/(1+eps) + h3[obj(r)]/(1+eps)
//                                   + sum_{adj} h5[j] / (deg+eps) ) / 3
__global__ __launch_bounds__(256)
void pred_final_kernel(const float* __restrict__ pred_feats,
                       const int*   __restrict__ rel_inds,
                       float* __restrict__ out_pred)
{
    __shared__ int s_sub[N_REL];
    __shared__ int s_obv[N_REL];
    const int tid = threadIdx.x;
    for (int t = tid; t < N_REL; t += 256) {
        s_sub[t] = rel_inds[2 * t + 0];
        s_obv[t] = rel_inds[2 * t + 1];
    }
    __syncthreads();

    const int r = blockIdx.x;
    const int my0 = s_sub[r];
    const int my1 = s_obv[r];

    float4 sum5[4];
#pragma unroll
    for (int q = 0; q < 4; q++) sum5[q] = make_float4(0.f, 0.f, 0.f, 0.f);
    int deg = 0;

    for (int j = 0; j < N_REL; j++) {
        if (j == r) continue;
        int a0 = s_sub[j], a1 = s_obv[j];
        bool adj = (a0 == my0) | (a1 == my1) | (a0 == my1) | (a1 == my0);
        if (adj) {
            deg++;
            const float* row = &g_h_pred[2][(size_t)j * DIM];
#pragma unroll
            for (int q = 0; q < 4; q++) {
                float4 v = *reinterpret_cast<const float4*>(row + q * 1024 + tid * 4);
                sum5[q].x += v.x; sum5[q].y += v.y; sum5[q].z += v.z; sum5[q].w += v.w;
            }
        }
    }

    const float invd  = 1.f / ((float)deg + EPSF);
    const float inv1e = 1.f / (1.f + EPSF);
    const float third = 1.f / 3.f;

    const float* h2row = &g_h_obj[1][(size_t)my0 * DIM];
    const float* h3row = &g_h_obj[2][(size_t)my1 * DIM];

#pragma unroll
    for (int q = 0; q < 4; q++) {
        int col = q * 1024 + tid * 4;
        float4 h2v = *reinterpret_cast<const float4*>(h2row + col);
        float4 h3v = *reinterpret_cast<const float4*>(h3row + col);
        float4 bs  = *reinterpret_cast<const float4*>(&pred_feats[(size_t)r * DIM + col]);
        float4 o;
        o.x = bs.x + ((h2v.x + h3v.x) * inv1e + sum5[q].x * invd) * third;
        o.y = bs.y + ((h2v.y + h3v.y) * inv1e + sum5[q].y * invd) * third;
        o.z = bs.z + ((h2v.z + h3v.z) * inv1e + sum5[q].z * invd) * third;
        o.w = bs.w + ((h2v.w + h3v.w) * inv1e + sum5[q].w * invd) * third;
        *reinterpret_cast<float4*>(&out_pred[(size_t)r * DIM + col]) = o;
    }
}

// ---------------- launch ----------------
extern "C" void kernel_launch(void* const* d_in, const int* in_sizes, int n_in,
                              void* d_out, int out_size)
{
    const float* obj_feats  = (const float*)d_in[0];  // [256,4096]
    const float* pred_feats = (const float*)d_in[1];  // [1024,4096]
    const int*   rel_inds   = (const int*)  d_in[2];  // [1024,2]
    const float* W_all      = (const float*)d_in[3];  // [6,4096,4096]
    const float* b_all      = (const float*)d_in[4];  // [6,4096]

    float* out_obj  = (float*)d_out;                        // [256,4096]
    float* out_pred = (float*)d_out + (size_t)N_OBJ * DIM;  // [1024,4096]

    // 3 pred-side GEMMs (W0, W1, W5), M=1024
    {
        dim3 grid(DIM / 128, N_REL / 128, 3);
        gemm_relu_nt<<<grid, 256>>>(pred_feats, W_all, b_all, N_REL, 0);
    }
    // 3 obj-side GEMMs (W4, W2, W3), M=256
    {
        dim3 grid(DIM / 128, N_OBJ / 128, 3);
        gemm_relu_nt<<<grid, 256>>>(obj_feats, W_all, b_all, N_OBJ, 1);
    }
    // column sums of h4
    colsum4_kernel<<<DIM / 256, 256>>>();
    // finals
    obj_final_kernel<<<N_OBJ, 256>>>(obj_feats, rel_inds, out_obj);
    pred_final_kernel<<<N_REL, 256>>>(pred_feats, rel_inds, out_pred);
}

// round 3
// speedup vs baseline: 2.4427x; 2.4427x over previous
#include <cuda_runtime.h>
#include <cuda_bf16.h>
#include <cstdint>

#define DIM   4096
#define N_OBJ 256
#define N_REL 1024
#define EPSF  1e-7f

// ---------------- scratch (static device arrays; no allocation) ----------------
__device__ float g_h_pred[3][(size_t)N_REL * DIM];
__device__ float g_h_obj[3][(size_t)N_OBJ * DIM];
__device__ float g_colsum4[DIM];
__device__ __nv_bfloat16 g_Whi[6ull * DIM * DIM];
__device__ __nv_bfloat16 g_Wlo[6ull * DIM * DIM];
__device__ __nv_bfloat16 g_Xphi[(size_t)N_REL * DIM];
__device__ __nv_bfloat16 g_Xplo[(size_t)N_REL * DIM];
__device__ __nv_bfloat16 g_Xohi[(size_t)N_OBJ * DIM];
__device__ __nv_bfloat16 g_Xolo[(size_t)N_OBJ * DIM];

// ---------------- helpers ----------------
__device__ __forceinline__ uint32_t smem_u32(const void* p) {
    uint32_t a;
    asm("{ .reg .u64 t; cvta.to.shared.u64 t, %1; cvt.u32.u64 %0, t; }"
        : "=r"(a) : "l"(p));
    return a;
}
#define CP16(dst, src) \
    asm volatile("cp.async.cg.shared.global [%0], [%1], 16;" :: "r"(dst), "l"(src) : "memory")
#define LDSM4(r, addr) \
    asm volatile("ldmatrix.sync.aligned.m8n8.x4.shared.b16 {%0,%1,%2,%3}, [%4];" \
        : "=r"((r)[0]), "=r"((r)[1]), "=r"((r)[2]), "=r"((r)[3]) : "r"(addr))

__device__ __forceinline__ void mma16816(float* c, const uint32_t* a,
                                         uint32_t b0, uint32_t b1) {
    asm volatile("mma.sync.aligned.m16n8k16.row.col.f32.bf16.bf16.f32 "
        "{%0,%1,%2,%3}, {%4,%5,%6,%7}, {%8,%9}, {%0,%1,%2,%3};"
        : "+f"(c[0]), "+f"(c[1]), "+f"(c[2]), "+f"(c[3])
        : "r"(a[0]), "r"(a[1]), "r"(a[2]), "r"(a[3]), "r"(b0), "r"(b1));
}

// ---------------- fp32 -> (hi,lo) bf16 split ----------------
__global__ void conv_split(const float4* __restrict__ src, int which, int n4)
{
    int i = blockIdx.x * blockDim.x + threadIdx.x;
    if (i >= n4) return;
    __nv_bfloat16 *hi, *lo;
    if (which == 0)      { hi = g_Whi;  lo = g_Wlo;  }
    else if (which == 1) { hi = g_Xphi; lo = g_Xplo; }
    else                 { hi = g_Xohi; lo = g_Xolo; }
    float4 v = src[i];
    __nv_bfloat16 h0 = __float2bfloat16(v.x), h1 = __float2bfloat16(v.y);
    __nv_bfloat16 h2 = __float2bfloat16(v.z), h3 = __float2bfloat16(v.w);
    __nv_bfloat16 l0 = __float2bfloat16(v.x - __bfloat162float(h0));
    __nv_bfloat16 l1 = __float2bfloat16(v.y - __bfloat162float(h1));
    __nv_bfloat16 l2 = __float2bfloat16(v.z - __bfloat162float(h2));
    __nv_bfloat16 l3 = __float2bfloat16(v.w - __bfloat162float(h3));
    __nv_bfloat162 H01 = __halves2bfloat162(h0, h1), H23 = __halves2bfloat162(h2, h3);
    __nv_bfloat162 L01 = __halves2bfloat162(l0, l1), L23 = __halves2bfloat162(l2, l3);
    uint2 H, L;
    H.x = *reinterpret_cast<uint32_t*>(&H01); H.y = *reinterpret_cast<uint32_t*>(&H23);
    L.x = *reinterpret_cast<uint32_t*>(&L01); L.y = *reinterpret_cast<uint32_t*>(&L23);
    reinterpret_cast<uint2*>(hi)[i] = H;
    reinterpret_cast<uint2*>(lo)[i] = L;
}

// ---------------- tensor-core GEMM: H = relu(X @ W^T + b) ----------------
// CTA tile 128x128, k-chunk 32 bf16. 8 warps, warp tile 64x32.
// smem tiles: pitch 80 B per row (conflict-free for ldmatrix + cp.async).
#define KC        32
#define PITCH     80
#define TILEB     (128 * PITCH)       // 10240 B per tile
#define BUFB      (4 * TILEB)         // Ah, Al, Bh, Bl
#define SMEM_DYN  (2 * BUFB)          // double buffered: 81920 B

__global__ __launch_bounds__(256)
void gemm_tc(const float* __restrict__ b_all)
{
    extern __shared__ char sm_raw[];
    const uint32_t tiles = smem_u32(sm_raw);

    const int tid  = threadIdx.x;
    const int wid  = tid >> 5;
    const int lane = tid & 31;
    const uint32_t lrow = lane & 15;
    const uint32_t lsel = lane >> 4;
    const int wm = (wid >> 2) * 64;    // 0 or 64
    const int wn = (wid & 3) * 32;     // 0..96

    const int slot = blockIdx.x;
    const int bn   = blockIdx.y * 128;
    int bm, widx;
    const __nv_bfloat16 *Ah, *Al;
    float* H;
    if (slot < 24) {
        int z = slot >> 3; bm = (slot & 7) * 128;
        Ah = g_Xphi; Al = g_Xplo; H = &g_h_pred[z][0];
        widx = (z == 2) ? 5 : z;
    } else {
        int s = slot - 24; int z = s >> 1; bm = (s & 1) * 128;
        Ah = g_Xohi; Al = g_Xolo; H = &g_h_obj[z][0];
        widx = (z == 0) ? 4 : (z + 1);
    }
    const char* gbase[4];
    gbase[0] = (const char*)Ah + (size_t)bm * (DIM * 2);
    gbase[1] = (const char*)Al + (size_t)bm * (DIM * 2);
    gbase[2] = (const char*)(g_Whi + (size_t)widx * DIM * DIM) + (size_t)bn * (DIM * 2);
    gbase[3] = (const char*)(g_Wlo + (size_t)widx * DIM * DIM) + (size_t)bn * (DIM * 2);
    const float* bias = b_all + (size_t)widx * DIM + bn;

    float c[4][4][4];
#pragma unroll
    for (int i = 0; i < 4; i++)
#pragma unroll
        for (int j = 0; j < 4; j++)
#pragma unroll
            for (int q = 0; q < 4; q++) c[i][j][q] = 0.f;

    const int NC = DIM / KC;   // 128 chunks

    // ---- preload chunk 0 ----
    {
        uint32_t dstb = tiles;
#pragma unroll
        for (int t = 0; t < 4; t++) {
#pragma unroll
            for (int it = 0; it < 2; it++) {
                int idx = tid + it * 256;
                int r = idx >> 2, u = idx & 3;
                CP16(dstb + t * TILEB + r * PITCH + u * 16,
                     gbase[t] + (size_t)r * (DIM * 2) + u * 16);
            }
        }
        asm volatile("cp.async.commit_group;" ::: "memory");
    }

    for (int kc = 0; kc < NC; kc++) {
        if (kc + 1 < NC) {
            uint32_t dstb = tiles + ((kc + 1) & 1) * BUFB;
            size_t koff = (size_t)(kc + 1) * (KC * 2);
#pragma unroll
            for (int t = 0; t < 4; t++) {
#pragma unroll
                for (int it = 0; it < 2; it++) {
                    int idx = tid + it * 256;
                    int r = idx >> 2, u = idx & 3;
                    CP16(dstb + t * TILEB + r * PITCH + u * 16,
                         gbase[t] + (size_t)r * (DIM * 2) + koff + u * 16);
                }
            }
            asm volatile("cp.async.commit_group;" ::: "memory");
            asm volatile("cp.async.wait_group 1;" ::: "memory");
        } else {
            asm volatile("cp.async.wait_group 0;" ::: "memory");
        }
        __syncthreads();

        const uint32_t bufb = tiles + (kc & 1) * BUFB;
#pragma unroll
        for (int ks = 0; ks < 2; ks++) {
            const uint32_t uoff = (ks * 2 + lsel) * 16;
            uint32_t ah[4][4], al[4][4];
#pragma unroll
            for (int i = 0; i < 4; i++) {
                uint32_t ra = bufb + (wm + 16 * i + lrow) * PITCH + uoff;
                LDSM4(ah[i], ra);
                LDSM4(al[i], ra + TILEB);
            }
            uint32_t bh[2][4], bl[2][4];
#pragma unroll
            for (int jj = 0; jj < 2; jj++) {
                uint32_t rb = bufb + 2 * TILEB + (wn + 16 * jj + lrow) * PITCH + uoff;
                LDSM4(bh[jj], rb);
                LDSM4(bl[jj], rb + TILEB);
            }
#pragma unroll
            for (int i = 0; i < 4; i++)
#pragma unroll
                for (int j = 0; j < 4; j++) {
                    const int jj = j >> 1, jo = j & 1;
                    mma16816(c[i][j], ah[i], bh[jj][jo], bh[jj][jo + 2]);
                    mma16816(c[i][j], ah[i], bl[jj][jo], bl[jj][jo + 2]);
                    mma16816(c[i][j], al[i], bh[jj][jo], bh[jj][jo + 2]);
                }
        }
        __syncthreads();
    }

    // ---- epilogue: bias + relu, direct stores ----
    const int qrow = lane >> 2;          // 0..7
    const int qcol = (lane & 3) * 2;     // 0,2,4,6
#pragma unroll
    for (int i = 0; i < 4; i++) {
        int grow0 = bm + wm + 16 * i + qrow;
#pragma unroll
        for (int j = 0; j < 4; j++) {
            int gcol = bn + wn + 8 * j + qcol;
            float b0 = bias[wn + 8 * j + qcol];
            float b1 = bias[wn + 8 * j + qcol + 1];
            float2 v0, v1;
            v0.x = fmaxf(c[i][j][0] + b0, 0.f);
            v0.y = fmaxf(c[i][j][1] + b1, 0.f);
            v1.x = fmaxf(c[i][j][2] + b0, 0.f);
            v1.y = fmaxf(c[i][j][3] + b1, 0.f);
            *reinterpret_cast<float2*>(H + (size_t)grow0 * DIM + gcol) = v0;
            *reinterpret_cast<float2*>(H + (size_t)(grow0 + 8) * DIM + gcol) = v1;
        }
    }
}

// ---------------- column sums of h4 ----------------
__global__ void colsum4_kernel()
{
    int c = blockIdx.x * blockDim.x + threadIdx.x;
    float s = 0.f;
    for (int r = 0; r < N_OBJ; r++) s += g_h_obj[0][(size_t)r * DIM + c];
    g_colsum4[c] = s;
}

// ---------------- obj side final ----------------
__global__ __launch_bounds__(256)
void obj_final_kernel(const float* __restrict__ obj_feats,
                      const int*   __restrict__ rel_inds,
                      float* __restrict__ out_obj)
{
    __shared__ int s_sub[N_REL];
    __shared__ int s_obv[N_REL];
    const int tid = threadIdx.x;
    for (int t = tid; t < N_REL; t += 256) {
        s_sub[t] = rel_inds[2 * t + 0];
        s_obv[t] = rel_inds[2 * t + 1];
    }
    __syncthreads();

    const int i = blockIdx.x;
    float4 sum0[4], sum1[4];
#pragma unroll
    for (int q = 0; q < 4; q++) {
        sum0[q] = make_float4(0.f, 0.f, 0.f, 0.f);
        sum1[q] = make_float4(0.f, 0.f, 0.f, 0.f);
    }
    int c0 = 0, c1 = 0;

    for (int r = 0; r < N_REL; r++) {
        if (s_sub[r] == i) {
            c0++;
            const float* row = &g_h_pred[0][(size_t)r * DIM];
#pragma unroll
            for (int q = 0; q < 4; q++) {
                float4 v = *reinterpret_cast<const float4*>(row + q * 1024 + tid * 4);
                sum0[q].x += v.x; sum0[q].y += v.y; sum0[q].z += v.z; sum0[q].w += v.w;
            }
        }
        if (s_obv[r] == i) {
            c1++;
            const float* row = &g_h_pred[1][(size_t)r * DIM];
#pragma unroll
            for (int q = 0; q < 4; q++) {
                float4 v = *reinterpret_cast<const float4*>(row + q * 1024 + tid * 4);
                sum1[q].x += v.x; sum1[q].y += v.y; sum1[q].z += v.z; sum1[q].w += v.w;
            }
        }
    }

    const float inv0 = 1.f / ((float)c0 + EPSF);
    const float inv1 = 1.f / ((float)c1 + EPSF);
    const float invo = 1.f / (255.f + EPSF);
    const float third = 1.f / 3.f;

#pragma unroll
    for (int q = 0; q < 4; q++) {
        int col = q * 1024 + tid * 4;
        float4 h4v = *reinterpret_cast<const float4*>(&g_h_obj[0][(size_t)i * DIM + col]);
        float4 cs  = *reinterpret_cast<const float4*>(&g_colsum4[col]);
        float4 bs  = *reinterpret_cast<const float4*>(&obj_feats[(size_t)i * DIM + col]);
        float4 o;
        o.x = bs.x + ((cs.x - h4v.x) * invo + sum0[q].x * inv0 + sum1[q].x * inv1) * third;
        o.y = bs.y + ((cs.y - h4v.y) * invo + sum0[q].y * inv0 + sum1[q].y * inv1) * third;
        o.z = bs.z + ((cs.z - h4v.z) * invo + sum0[q].z * inv0 + sum1[q].z * inv1) * third;
        o.w = bs.w + ((cs.w - h4v.w) * invo + sum0[q].w * inv0 + sum1[q].w * inv1) * third;
        *reinterpret_cast<float4*>(&out_obj[(size_t)i * DIM + col]) = o;
    }
}

// ---------------- pred side final ----------------
__global__ __launch_bounds__(256)
void pred_final_kernel(const float* __restrict__ pred_feats,
                       const int*   __restrict__ rel_inds,
                       float* __restrict__ out_pred)
{
    __shared__ int s_sub[N_REL];
    __shared__ int s_obv[N_REL];
    const int tid = threadIdx.x;
    for (int t = tid; t < N_REL; t += 256) {
        s_sub[t] = rel_inds[2 * t + 0];
        s_obv[t] = rel_inds[2 * t + 1];
    }
    __syncthreads();

    const int r = blockIdx.x;
    const int my0 = s_sub[r];
    const int my1 = s_obv[r];

    float4 sum5[4];
#pragma unroll
    for (int q = 0; q < 4; q++) sum5[q] = make_float4(0.f, 0.f, 0.f, 0.f);
    int deg = 0;

    for (int j = 0; j < N_REL; j++) {
        if (j == r) continue;
        int a0 = s_sub[j], a1 = s_obv[j];
        bool adj = (a0 == my0) | (a1 == my1) | (a0 == my1) | (a1 == my0);
        if (adj) {
            deg++;
            const float* row = &g_h_pred[2][(size_t)j * DIM];
#pragma unroll
            for (int q = 0; q < 4; q++) {
                float4 v = *reinterpret_cast<const float4*>(row + q * 1024 + tid * 4);
                sum5[q].x += v.x; sum5[q].y += v.y; sum5[q].z += v.z; sum5[q].w += v.w;
            }
        }
    }

    const float invd  = 1.f / ((float)deg + EPSF);
    const float inv1e = 1.f / (1.f + EPSF);
    const float third = 1.f / 3.f;

    const float* h2row = &g_h_obj[1][(size_t)my0 * DIM];
    const float* h3row = &g_h_obj[2][(size_t)my1 * DIM];

#pragma unroll
    for (int q = 0; q < 4; q++) {
        int col = q * 1024 + tid * 4;
        float4 h2v = *reinterpret_cast<const float4*>(h2row + col);
        float4 h3v = *reinterpret_cast<const float4*>(h3row + col);
        float4 bs  = *reinterpret_cast<const float4*>(&pred_feats[(size_t)r * DIM + col]);
        float4 o;
        o.x = bs.x + ((h2v.x + h3v.x) * inv1e + sum5[q].x * invd) * third;
        o.y = bs.y + ((h2v.y + h3v.y) * inv1e + sum5[q].y * invd) * third;
        o.z = bs.z + ((h2v.z + h3v.z) * inv1e + sum5[q].z * invd) * third;
        o.w = bs.w + ((h2v.w + h3v.w) * inv1e + sum5[q].w * invd) * third;
        *reinterpret_cast<float4*>(&out_pred[(size_t)r * DIM + col]) = o;
    }
}

// ---------------- launch ----------------
extern "C" void kernel_launch(void* const* d_in, const int* in_sizes, int n_in,
                              void* d_out, int out_size)
{
    const float* obj_feats  = (const float*)d_in[0];
    const float* pred_feats = (const float*)d_in[1];
    const int*   rel_inds   = (const int*)  d_in[2];
    const float* W_all      = (const float*)d_in[3];
    const float* b_all      = (const float*)d_in[4];

    float* out_obj  = (float*)d_out;
    float* out_pred = (float*)d_out + (size_t)N_OBJ * DIM;

    cudaFuncSetAttribute(gemm_tc, cudaFuncAttributeMaxDynamicSharedMemorySize, SMEM_DYN);

    int n4W = 6 * DIM * DIM / 4;
    conv_split<<<(n4W + 255) / 256, 256>>>((const float4*)W_all, 0, n4W);
    int n4P = N_REL * DIM / 4;
    conv_split<<<(n4P + 255) / 256, 256>>>((const float4*)pred_feats, 1, n4P);
    int n4O = N_OBJ * DIM / 4;
    conv_split<<<(n4O + 255) / 256, 256>>>((const float4*)obj_feats, 2, n4O);

    gemm_tc<<<dim3(30, 32), 256, SMEM_DYN>>>(b_all);

    colsum4_kernel<<<DIM / 256, 256>>>();
    obj_final_kernel<<<N_OBJ, 256>>>(obj_feats, rel_inds, out_obj);
    pred_final_kernel<<<N_REL, 256>>>(pred_feats, rel_inds, out_pred);
}

// round 4
// speedup vs baseline: 2.4836x; 1.0167x over previous
#include <cuda_runtime.h>
#include <cuda_bf16.h>
#include <cstdint>

#define DIM   4096
#define N_OBJ 256
#define N_REL 1024
#define EPSF  1e-7f

// ---------------- scratch (static device arrays; no allocation) ----------------
__device__ float g_h_pred[3][(size_t)N_REL * DIM];
__device__ float g_h_obj[3][(size_t)N_OBJ * DIM];
__device__ float g_colsum4[DIM];
__device__ __nv_bfloat16 g_Whi[6ull * DIM * DIM];
__device__ __nv_bfloat16 g_Wlo[6ull * DIM * DIM];
__device__ __nv_bfloat16 g_Xphi[(size_t)N_REL * DIM];
__device__ __nv_bfloat16 g_Xplo[(size_t)N_REL * DIM];
__device__ __nv_bfloat16 g_Xohi[(size_t)N_OBJ * DIM];
__device__ __nv_bfloat16 g_Xolo[(size_t)N_OBJ * DIM];

// ---------------- helpers ----------------
__device__ __forceinline__ uint32_t smem_u32(const void* p) {
    uint32_t a;
    asm("{ .reg .u64 t; cvta.to.shared.u64 t, %1; cvt.u32.u64 %0, t; }"
        : "=r"(a) : "l"(p));
    return a;
}
#define CP16(dst, src) \
    asm volatile("cp.async.cg.shared.global [%0], [%1], 16;" :: "r"(dst), "l"(src) : "memory")
#define LDSM4(r, addr) \
    asm volatile("ldmatrix.sync.aligned.m8n8.x4.shared.b16 {%0,%1,%2,%3}, [%4];" \
        : "=r"((r)[0]), "=r"((r)[1]), "=r"((r)[2]), "=r"((r)[3]) : "r"(addr))

__device__ __forceinline__ void mma16816(float* c, const uint32_t* a,
                                         uint32_t b0, uint32_t b1) {
    asm volatile("mma.sync.aligned.m16n8k16.row.col.f32.bf16.bf16.f32 "
        "{%0,%1,%2,%3}, {%4,%5,%6,%7}, {%8,%9}, {%0,%1,%2,%3};"
        : "+f"(c[0]), "+f"(c[1]), "+f"(c[2]), "+f"(c[3])
        : "r"(a[0]), "r"(a[1]), "r"(a[2]), "r"(a[3]), "r"(b0), "r"(b1));
}

// ---------------- fp32 -> (hi,lo) bf16 split ----------------
__global__ void conv_split(const float4* __restrict__ src, int which, int n4)
{
    int i = blockIdx.x * blockDim.x + threadIdx.x;
    if (i >= n4) return;
    __nv_bfloat16 *hi, *lo;
    if (which == 0)      { hi = g_Whi;  lo = g_Wlo;  }
    else if (which == 1) { hi = g_Xphi; lo = g_Xplo; }
    else                 { hi = g_Xohi; lo = g_Xolo; }
    float4 v = src[i];
    __nv_bfloat16 h0 = __float2bfloat16(v.x), h1 = __float2bfloat16(v.y);
    __nv_bfloat16 h2 = __float2bfloat16(v.z), h3 = __float2bfloat16(v.w);
    __nv_bfloat16 l0 = __float2bfloat16(v.x - __bfloat162float(h0));
    __nv_bfloat16 l1 = __float2bfloat16(v.y - __bfloat162float(h1));
    __nv_bfloat16 l2 = __float2bfloat16(v.z - __bfloat162float(h2));
    __nv_bfloat16 l3 = __float2bfloat16(v.w - __bfloat162float(h3));
    __nv_bfloat162 H01 = __halves2bfloat162(h0, h1), H23 = __halves2bfloat162(h2, h3);
    __nv_bfloat162 L01 = __halves2bfloat162(l0, l1), L23 = __halves2bfloat162(l2, l3);
    uint2 H, L;
    H.x = *reinterpret_cast<uint32_t*>(&H01); H.y = *reinterpret_cast<uint32_t*>(&H23);
    L.x = *reinterpret_cast<uint32_t*>(&L01); L.y = *reinterpret_cast<uint32_t*>(&L23);
    reinterpret_cast<uint2*>(hi)[i] = H;
    reinterpret_cast<uint2*>(lo)[i] = L;
}

// ---------------- tensor-core GEMM: H = relu(X @ W^T + b) ----------------
// CTA tile 128x128, k-chunk 32 bf16. 8 warps, warp tile 64x32.
// smem pitch 80 B/row (conflict-free ldmatrix). Double-buffered, 1 barrier/chunk.
#define KC        32
#define PITCH     80
#define TILEB     (128 * PITCH)       // 10240 B per tile
#define BUFB      (4 * TILEB)         // Ah, Al, Bh, Bl
#define SMEM_DYN  (2 * BUFB)          // 81920 B

__global__ __launch_bounds__(256, 2)
void gemm_tc(const float* __restrict__ b_all)
{
    extern __shared__ char sm_raw[];
    const uint32_t tiles = smem_u32(sm_raw);

    const int tid  = threadIdx.x;
    const int wid  = tid >> 5;
    const int lane = tid & 31;
    const uint32_t lrow = lane & 15;
    const uint32_t lsel = lane >> 4;
    const int wm = (wid >> 2) * 64;    // 0 or 64
    const int wn = (wid & 3) * 32;     // 0..96

    const int slot = blockIdx.x;
    const int bn   = blockIdx.y * 128;
    int bm, widx;
    const __nv_bfloat16 *Ah, *Al;
    float* H;
    if (slot < 24) {
        int z = slot >> 3; bm = (slot & 7) * 128;
        Ah = g_Xphi; Al = g_Xplo; H = &g_h_pred[z][0];
        widx = (z == 2) ? 5 : z;
    } else {
        int s = slot - 24; int z = s >> 1; bm = (s & 1) * 128;
        Ah = g_Xohi; Al = g_Xolo; H = &g_h_obj[z][0];
        widx = (z == 0) ? 4 : (z + 1);
    }
    const char* gbase[4];
    gbase[0] = (const char*)Ah + (size_t)bm * (DIM * 2);
    gbase[1] = (const char*)Al + (size_t)bm * (DIM * 2);
    gbase[2] = (const char*)(g_Whi + (size_t)widx * DIM * DIM) + (size_t)bn * (DIM * 2);
    gbase[3] = (const char*)(g_Wlo + (size_t)widx * DIM * DIM) + (size_t)bn * (DIM * 2);
    const float* bias = b_all + (size_t)widx * DIM + bn;

    float c[4][4][4];
#pragma unroll
    for (int i = 0; i < 4; i++)
#pragma unroll
        for (int j = 0; j < 4; j++)
#pragma unroll
            for (int q = 0; q < 4; q++) c[i][j][q] = 0.f;

    const int NC = DIM / KC;   // 128 chunks
    const int r_ld = tid >> 2, u_ld = tid & 3;   // cp.async layout

    // ---- preload chunk 0 ----
#pragma unroll
    for (int t = 0; t < 4; t++) {
        CP16(tiles + t * TILEB + r_ld * PITCH + u_ld * 16,
             gbase[t] + (size_t)r_ld * (DIM * 2) + u_ld * 16);
        CP16(tiles + t * TILEB + (r_ld + 64) * PITCH + u_ld * 16,
             gbase[t] + (size_t)(r_ld + 64) * (DIM * 2) + u_ld * 16);
    }
    asm volatile("cp.async.commit_group;" ::: "memory");

    for (int kc = 0; kc < NC; kc++) {
        // publish buf[kc] + retire buf[kc-1] readers: ONE barrier per chunk
        asm volatile("cp.async.wait_group 0;" ::: "memory");
        __syncthreads();

        if (kc + 1 < NC) {
            uint32_t dstb = tiles + ((kc + 1) & 1) * BUFB;
            size_t koff = (size_t)(kc + 1) * (KC * 2);
#pragma unroll
            for (int t = 0; t < 4; t++) {
                CP16(dstb + t * TILEB + r_ld * PITCH + u_ld * 16,
                     gbase[t] + (size_t)r_ld * (DIM * 2) + koff + u_ld * 16);
                CP16(dstb + t * TILEB + (r_ld + 64) * PITCH + u_ld * 16,
                     gbase[t] + (size_t)(r_ld + 64) * (DIM * 2) + koff + u_ld * 16);
            }
            asm volatile("cp.async.commit_group;" ::: "memory");
        }

        const uint32_t bufb = tiles + (kc & 1) * BUFB;
#pragma unroll
        for (int ks = 0; ks < 2; ks++) {
            const uint32_t uoff = (ks * 2 + lsel) * 16;
            // B fragments for this ks (shared across all i-blocks)
            uint32_t bh[2][4], bl[2][4];
#pragma unroll
            for (int jj = 0; jj < 2; jj++) {
                uint32_t rb = bufb + 2 * TILEB + (wn + 16 * jj + lrow) * PITCH + uoff;
                LDSM4(bh[jj], rb);
                LDSM4(bl[jj], rb + TILEB);
            }
            // A fragments: double-buffered per i-block, skewed prefetch
            uint32_t ah[2][4], al[2][4];
            {
                uint32_t ra = bufb + (wm + lrow) * PITCH + uoff;
                LDSM4(ah[0], ra);
                LDSM4(al[0], ra + TILEB);
            }
#pragma unroll
            for (int i = 0; i < 4; i++) {
                if (i < 3) {
                    uint32_t ra = bufb + (wm + 16 * (i + 1) + lrow) * PITCH + uoff;
                    LDSM4(ah[(i + 1) & 1], ra);
                    LDSM4(al[(i + 1) & 1], ra + TILEB);
                }
                const uint32_t* Ah_ = ah[i & 1];
                const uint32_t* Al_ = al[i & 1];
#pragma unroll
                for (int j = 0; j < 4; j++) {
                    const int jj = j >> 1, jo = j & 1;
                    mma16816(c[i][j], Ah_, bh[jj][jo], bh[jj][jo + 2]);
                    mma16816(c[i][j], Ah_, bl[jj][jo], bl[jj][jo + 2]);
                    mma16816(c[i][j], Al_, bh[jj][jo], bh[jj][jo + 2]);
                }
            }
        }
    }

    // ---- epilogue: bias + relu, direct stores ----
    const int qrow = lane >> 2;          // 0..7
    const int qcol = (lane & 3) * 2;     // 0,2,4,6
#pragma unroll
    for (int i = 0; i < 4; i++) {
        int grow0 = bm + wm + 16 * i + qrow;
#pragma unroll
        for (int j = 0; j < 4; j++) {
            int gcol = bn + wn + 8 * j + qcol;
            float b0 = bias[wn + 8 * j + qcol];
            float b1 = bias[wn + 8 * j + qcol + 1];
            float2 v0, v1;
            v0.x = fmaxf(c[i][j][0] + b0, 0.f);
            v0.y = fmaxf(c[i][j][1] + b1, 0.f);
            v1.x = fmaxf(c[i][j][2] + b0, 0.f);
            v1.y = fmaxf(c[i][j][3] + b1, 0.f);
            *reinterpret_cast<float2*>(H + (size_t)grow0 * DIM + gcol) = v0;
            *reinterpret_cast<float2*>(H + (size_t)(grow0 + 8) * DIM + gcol) = v1;
        }
    }
}

// ---------------- column sums of h4 ----------------
__global__ void colsum4_kernel()
{
    int c = blockIdx.x * blockDim.x + threadIdx.x;
    float s = 0.f;
    for (int r = 0; r < N_OBJ; r++) s += g_h_obj[0][(size_t)r * DIM + c];
    g_colsum4[c] = s;
}

// ---------------- obj side final ----------------
__global__ __launch_bounds__(256)
void obj_final_kernel(const float* __restrict__ obj_feats,
                      const int*   __restrict__ rel_inds,
                      float* __restrict__ out_obj)
{
    __shared__ int s_sub[N_REL];
    __shared__ int s_obv[N_REL];
    const int tid = threadIdx.x;
    for (int t = tid; t < N_REL; t += 256) {
        s_sub[t] = rel_inds[2 * t + 0];
        s_obv[t] = rel_inds[2 * t + 1];
    }
    __syncthreads();

    const int i = blockIdx.x;
    float4 sum0[4], sum1[4];
#pragma unroll
    for (int q = 0; q < 4; q++) {
        sum0[q] = make_float4(0.f, 0.f, 0.f, 0.f);
        sum1[q] = make_float4(0.f, 0.f, 0.f, 0.f);
    }
    int c0 = 0, c1 = 0;

    for (int r = 0; r < N_REL; r++) {
        if (s_sub[r] == i) {
            c0++;
            const float* row = &g_h_pred[0][(size_t)r * DIM];
#pragma unroll
            for (int q = 0; q < 4; q++) {
                float4 v = *reinterpret_cast<const float4*>(row + q * 1024 + tid * 4);
                sum0[q].x += v.x; sum0[q].y += v.y; sum0[q].z += v.z; sum0[q].w += v.w;
            }
        }
        if (s_obv[r] == i) {
            c1++;
            const float* row = &g_h_pred[1][(size_t)r * DIM];
#pragma unroll
            for (int q = 0; q < 4; q++) {
                float4 v = *reinterpret_cast<const float4*>(row + q * 1024 + tid * 4);
                sum1[q].x += v.x; sum1[q].y += v.y; sum1[q].z += v.z; sum1[q].w += v.w;
            }
        }
    }

    const float inv0 = 1.f / ((float)c0 + EPSF);
    const float inv1 = 1.f / ((float)c1 + EPSF);
    const float invo = 1.f / (255.f + EPSF);
    const float third = 1.f / 3.f;

#pragma unroll
    for (int q = 0; q < 4; q++) {
        int col = q * 1024 + tid * 4;
        float4 h4v = *reinterpret_cast<const float4*>(&g_h_obj[0][(size_t)i * DIM + col]);
        float4 cs  = *reinterpret_cast<const float4*>(&g_colsum4[col]);
        float4 bs  = *reinterpret_cast<const float4*>(&obj_feats[(size_t)i * DIM + col]);
        float4 o;
        o.x = bs.x + ((cs.x - h4v.x) * invo + sum0[q].x * inv0 + sum1[q].x * inv1) * third;
        o.y = bs.y + ((cs.y - h4v.y) * invo + sum0[q].y * inv0 + sum1[q].y * inv1) * third;
        o.z = bs.z + ((cs.z - h4v.z) * invo + sum0[q].z * inv0 + sum1[q].z * inv1) * third;
        o.w = bs.w + ((cs.w - h4v.w) * invo + sum0[q].w * inv0 + sum1[q].w * inv1) * third;
        *reinterpret_cast<float4*>(&out_obj[(size_t)i * DIM + col]) = o;
    }
}

// ---------------- pred side final ----------------
__global__ __launch_bounds__(256)
void pred_final_kernel(const float* __restrict__ pred_feats,
                       const int*   __restrict__ rel_inds,
                       float* __restrict__ out_pred)
{
    __shared__ int s_sub[N_REL];
    __shared__ int s_obv[N_REL];
    const int tid = threadIdx.x;
    for (int t = tid; t < N_REL; t += 256) {
        s_sub[t] = rel_inds[2 * t + 0];
        s_obv[t] = rel_inds[2 * t + 1];
    }
    __syncthreads();

    const int r = blockIdx.x;
    const int my0 = s_sub[r];
    const int my1 = s_obv[r];

    float4 sum5[4];
#pragma unroll
    for (int q = 0; q < 4; q++) sum5[q] = make_float4(0.f, 0.f, 0.f, 0.f);
    int deg = 0;

    for (int j = 0; j < N_REL; j++) {
        if (j == r) continue;
        int a0 = s_sub[j], a1 = s_obv[j];
        bool adj = (a0 == my0) | (a1 == my1) | (a0 == my1) | (a1 == my0);
        if (adj) {
            deg++;
            const float* row = &g_h_pred[2][(size_t)j * DIM];
#pragma unroll
            for (int q = 0; q < 4; q++) {
                float4 v = *reinterpret_cast<const float4*>(row + q * 1024 + tid * 4);
                sum5[q].x += v.x; sum5[q].y += v.y; sum5[q].z += v.z; sum5[q].w += v.w;
            }
        }
    }

    const float invd  = 1.f / ((float)deg + EPSF);
    const float inv1e = 1.f / (1.f + EPSF);
    const float third = 1.f / 3.f;

    const float* h2row = &g_h_obj[1][(size_t)my0 * DIM];
    const float* h3row = &g_h_obj[2][(size_t)my1 * DIM];

#pragma unroll
    for (int q = 0; q < 4; q++) {
        int col = q * 1024 + tid * 4;
        float4 h2v = *reinterpret_cast<const float4*>(h2row + col);
        float4 h3v = *reinterpret_cast<const float4*>(h3row + col);
        float4 bs  = *reinterpret_cast<const float4*>(&pred_feats[(size_t)r * DIM + col]);
        float4 o;
        o.x = bs.x + ((h2v.x + h3v.x) * inv1e + sum5[q].x * invd) * third;
        o.y = bs.y + ((h2v.y + h3v.y) * inv1e + sum5[q].y * invd) * third;
        o.z = bs.z + ((h2v.z + h3v.z) * inv1e + sum5[q].z * invd) * third;
        o.w = bs.w + ((h2v.w + h3v.w) * inv1e + sum5[q].w * invd) * third;
        *reinterpret_cast<float4*>(&out_pred[(size_t)r * DIM + col]) = o;
    }
}

// ---------------- launch ----------------
extern "C" void kernel_launch(void* const* d_in, const int* in_sizes, int n_in,
                              void* d_out, int out_size)
{
    const float* obj_feats  = (const float*)d_in[0];
    const float* pred_feats = (const float*)d_in[1];
    const int*   rel_inds   = (const int*)  d_in[2];
    const float* W_all      = (const float*)d_in[3];
    const float* b_all      = (const float*)d_in[4];

    float* out_obj  = (float*)d_out;
    float* out_pred = (float*)d_out + (size_t)N_OBJ * DIM;

    cudaFuncSetAttribute(gemm_tc, cudaFuncAttributeMaxDynamicSharedMemorySize, SMEM_DYN);

    int n4W = 6 * DIM * DIM / 4;
    conv_split<<<(n4W + 255) / 256, 256>>>((const float4*)W_all, 0, n4W);
    int n4P = N_REL * DIM / 4;
    conv_split<<<(n4P + 255) / 256, 256>>>((const float4*)pred_feats, 1, n4P);
    int n4O = N_OBJ * DIM / 4;
    conv_split<<<(n4O + 255) / 256, 256>>>((const float4*)obj_feats, 2, n4O);

    gemm_tc<<<dim3(30, 32), 256, SMEM_DYN>>>(b_all);

    colsum4_kernel<<<DIM / 256, 256>>>();
    obj_final_kernel<<<N_OBJ, 256>>>(obj_feats, rel_inds, out_obj);
    pred_final_kernel<<<N_REL, 256>>>(pred_feats, rel_inds, out_pred);
}

// round 5
// speedup vs baseline: 3.3320x; 1.3416x over previous
#include <cuda_runtime.h>
#include <cuda_fp16.h>
#include <cstdint>

#define DIM   4096
#define N_OBJ 256
#define N_REL 1024
#define EPSF  1e-7f

// ---------------- scratch (static device arrays; no allocation) ----------------
__device__ float g_h_pred[3][(size_t)N_REL * DIM];
__device__ float g_h_obj[3][(size_t)N_OBJ * DIM];
__device__ float g_colsum4[DIM];
__device__ __half g_Wh[6ull * DIM * DIM];
__device__ __half g_Xph[(size_t)N_REL * DIM];
__device__ __half g_Xpl[(size_t)N_REL * DIM];
__device__ __half g_Xoh[(size_t)N_OBJ * DIM];
__device__ __half g_Xol[(size_t)N_OBJ * DIM];

// ---------------- helpers ----------------
__device__ __forceinline__ uint32_t smem_u32(const void* p) {
    uint32_t a;
    asm("{ .reg .u64 t; cvta.to.shared.u64 t, %1; cvt.u32.u64 %0, t; }"
        : "=r"(a) : "l"(p));
    return a;
}
#define CP16(dst, src) \
    asm volatile("cp.async.cg.shared.global [%0], [%1], 16;" :: "r"(dst), "l"(src) : "memory")
#define LDSM4(r, addr) \
    asm volatile("ldmatrix.sync.aligned.m8n8.x4.shared.b16 {%0,%1,%2,%3}, [%4];" \
        : "=r"((r)[0]), "=r"((r)[1]), "=r"((r)[2]), "=r"((r)[3]) : "r"(addr))

__device__ __forceinline__ void mma16816(float* c, const uint32_t* a,
                                         uint32_t b0, uint32_t b1) {
    asm volatile("mma.sync.aligned.m16n8k16.row.col.f32.f16.f16.f32 "
        "{%0,%1,%2,%3}, {%4,%5,%6,%7}, {%8,%9}, {%0,%1,%2,%3};"
        : "+f"(c[0]), "+f"(c[1]), "+f"(c[2]), "+f"(c[3])
        : "r"(a[0]), "r"(a[1]), "r"(a[2]), "r"(a[3]), "r"(b0), "r"(b1));
}

// ---------------- fp32 -> fp16 (W: hi only) ----------------
__global__ void conv_w(const float4* __restrict__ src, int n4)
{
    int i = blockIdx.x * blockDim.x + threadIdx.x;
    if (i >= n4) return;
    float4 v = src[i];
    __half2 h01 = __floats2half2_rn(v.x, v.y);
    __half2 h23 = __floats2half2_rn(v.z, v.w);
    uint2 H;
    H.x = *reinterpret_cast<uint32_t*>(&h01);
    H.y = *reinterpret_cast<uint32_t*>(&h23);
    reinterpret_cast<uint2*>(g_Wh)[i] = H;
}

// ---------------- fp32 -> (hi,lo) fp16 split (X) ----------------
__global__ void conv_x(const float4* __restrict__ src, int which, int n4)
{
    int i = blockIdx.x * blockDim.x + threadIdx.x;
    if (i >= n4) return;
    __half *hi, *lo;
    if (which == 0) { hi = g_Xph; lo = g_Xpl; }
    else            { hi = g_Xoh; lo = g_Xol; }
    float4 v = src[i];
    __half h0 = __float2half_rn(v.x), h1 = __float2half_rn(v.y);
    __half h2 = __float2half_rn(v.z), h3 = __float2half_rn(v.w);
    __half l0 = __float2half_rn(v.x - __half2float(h0));
    __half l1 = __float2half_rn(v.y - __half2float(h1));
    __half l2 = __float2half_rn(v.z - __half2float(h2));
    __half l3 = __float2half_rn(v.w - __half2float(h3));
    __half2 H01 = __halves2half2(h0, h1), H23 = __halves2half2(h2, h3);
    __half2 L01 = __halves2half2(l0, l1), L23 = __halves2half2(l2, l3);
    uint2 H, L;
    H.x = *reinterpret_cast<uint32_t*>(&H01); H.y = *reinterpret_cast<uint32_t*>(&H23);
    L.x = *reinterpret_cast<uint32_t*>(&L01); L.y = *reinterpret_cast<uint32_t*>(&L23);
    reinterpret_cast<uint2*>(hi)[i] = H;
    reinterpret_cast<uint2*>(lo)[i] = L;
}

// ---------------- tensor-core GEMM: H = relu(X @ W^T + b) ----------------
// CTA tile 128x128, k-chunk 32 fp16. 8 warps, warp tile 64x32.
// 3 smem tiles (Xh, Xl, Wh), pitch 80 B/row, double-buffered, 1 barrier/chunk.
#define KC        32
#define PITCH     80
#define TILEB     (128 * PITCH)       // 10240 B per tile
#define BUFB      (3 * TILEB)         // Xh, Xl, Wh
#define SMEM_DYN  (2 * BUFB)          // 61440 B

__global__ __launch_bounds__(256, 2)
void gemm_tc(const float* __restrict__ b_all)
{
    extern __shared__ char sm_raw[];
    const uint32_t tiles = smem_u32(sm_raw);

    const int tid  = threadIdx.x;
    const int wid  = tid >> 5;
    const int lane = tid & 31;
    const uint32_t lrow = lane & 15;
    const uint32_t lsel = lane >> 4;
    const int wm = (wid >> 2) * 64;    // 0 or 64
    const int wn = (wid & 3) * 32;     // 0..96

    const int slot = blockIdx.x;
    const int bn   = blockIdx.y * 128;
    int bm, widx;
    const __half *Ah, *Al;
    float* H;
    if (slot < 24) {
        int z = slot >> 3; bm = (slot & 7) * 128;
        Ah = g_Xph; Al = g_Xpl; H = &g_h_pred[z][0];
        widx = (z == 2) ? 5 : z;
    } else {
        int s = slot - 24; int z = s >> 1; bm = (s & 1) * 128;
        Ah = g_Xoh; Al = g_Xol; H = &g_h_obj[z][0];
        widx = (z == 0) ? 4 : (z + 1);
    }
    const char* gbase[3];
    gbase[0] = (const char*)Ah + (size_t)bm * (DIM * 2);
    gbase[1] = (const char*)Al + (size_t)bm * (DIM * 2);
    gbase[2] = (const char*)(g_Wh + (size_t)widx * DIM * DIM) + (size_t)bn * (DIM * 2);
    const float* bias = b_all + (size_t)widx * DIM + bn;

    float c[4][4][4];
#pragma unroll
    for (int i = 0; i < 4; i++)
#pragma unroll
        for (int j = 0; j < 4; j++)
#pragma unroll
            for (int q = 0; q < 4; q++) c[i][j][q] = 0.f;

    const int NC = DIM / KC;   // 128 chunks
    const int r_ld = tid >> 2, u_ld = tid & 3;

    // ---- preload chunk 0 ----
#pragma unroll
    for (int t = 0; t < 3; t++) {
        CP16(tiles + t * TILEB + r_ld * PITCH + u_ld * 16,
             gbase[t] + (size_t)r_ld * (DIM * 2) + u_ld * 16);
        CP16(tiles + t * TILEB + (r_ld + 64) * PITCH + u_ld * 16,
             gbase[t] + (size_t)(r_ld + 64) * (DIM * 2) + u_ld * 16);
    }
    asm volatile("cp.async.commit_group;" ::: "memory");

    for (int kc = 0; kc < NC; kc++) {
        asm volatile("cp.async.wait_group 0;" ::: "memory");
        __syncthreads();

        if (kc + 1 < NC) {
            uint32_t dstb = tiles + ((kc + 1) & 1) * BUFB;
            size_t koff = (size_t)(kc + 1) * (KC * 2);
#pragma unroll
            for (int t = 0; t < 3; t++) {
                CP16(dstb + t * TILEB + r_ld * PITCH + u_ld * 16,
                     gbase[t] + (size_t)r_ld * (DIM * 2) + koff + u_ld * 16);
                CP16(dstb + t * TILEB + (r_ld + 64) * PITCH + u_ld * 16,
                     gbase[t] + (size_t)(r_ld + 64) * (DIM * 2) + koff + u_ld * 16);
            }
            asm volatile("cp.async.commit_group;" ::: "memory");
        }

        const uint32_t bufb = tiles + (kc & 1) * BUFB;
#pragma unroll
        for (int ks = 0; ks < 2; ks++) {
            const uint32_t uoff = (ks * 2 + lsel) * 16;
            // B fragments (Wh only)
            uint32_t bh[2][4];
#pragma unroll
            for (int jj = 0; jj < 2; jj++) {
                uint32_t rb = bufb + 2 * TILEB + (wn + 16 * jj + lrow) * PITCH + uoff;
                LDSM4(bh[jj], rb);
            }
            // A fragments: all 4 i-blocks, hi and lo
            uint32_t ah[4][4], al[4][4];
#pragma unroll
            for (int i = 0; i < 4; i++) {
                uint32_t ra = bufb + (wm + 16 * i + lrow) * PITCH + uoff;
                LDSM4(ah[i], ra);
                LDSM4(al[i], ra + TILEB);
            }
            // term-major: 16 independent hh MMAs, then 16 independent lh MMAs
#pragma unroll
            for (int i = 0; i < 4; i++)
#pragma unroll
                for (int j = 0; j < 4; j++) {
                    const int jj = j >> 1, jo = j & 1;
                    mma16816(c[i][j], ah[i], bh[jj][jo], bh[jj][jo + 2]);
                }
#pragma unroll
            for (int i = 0; i < 4; i++)
#pragma unroll
                for (int j = 0; j < 4; j++) {
                    const int jj = j >> 1, jo = j & 1;
                    mma16816(c[i][j], al[i], bh[jj][jo], bh[jj][jo + 2]);
                }
        }
    }

    // ---- epilogue: bias + relu, direct stores ----
    const int qrow = lane >> 2;          // 0..7
    const int qcol = (lane & 3) * 2;     // 0,2,4,6
#pragma unroll
    for (int i = 0; i < 4; i++) {
        int grow0 = bm + wm + 16 * i + qrow;
#pragma unroll
        for (int j = 0; j < 4; j++) {
            int gcol = bn + wn + 8 * j + qcol;
            float b0 = bias[wn + 8 * j + qcol];
            float b1 = bias[wn + 8 * j + qcol + 1];
            float2 v0, v1;
            v0.x = fmaxf(c[i][j][0] + b0, 0.f);
            v0.y = fmaxf(c[i][j][1] + b1, 0.f);
            v1.x = fmaxf(c[i][j][2] + b0, 0.f);
            v1.y = fmaxf(c[i][j][3] + b1, 0.f);
            *reinterpret_cast<float2*>(H + (size_t)grow0 * DIM + gcol) = v0;
            *reinterpret_cast<float2*>(H + (size_t)(grow0 + 8) * DIM + gcol) = v1;
        }
    }
}

// ---------------- column sums of h4 ----------------
__global__ void colsum4_kernel()
{
    int c = blockIdx.x * blockDim.x + threadIdx.x;
    float s = 0.f;
    for (int r = 0; r < N_OBJ; r++) s += g_h_obj[0][(size_t)r * DIM + c];
    g_colsum4[c] = s;
}

// ---------------- obj side final ----------------
__global__ __launch_bounds__(256)
void obj_final_kernel(const float* __restrict__ obj_feats,
                      const int*   __restrict__ rel_inds,
                      float* __restrict__ out_obj)
{
    __shared__ int s_sub[N_REL];
    __shared__ int s_obv[N_REL];
    const int tid = threadIdx.x;
    for (int t = tid; t < N_REL; t += 256) {
        s_sub[t] = rel_inds[2 * t + 0];
        s_obv[t] = rel_inds[2 * t + 1];
    }
    __syncthreads();

    const int i = blockIdx.x;
    float4 sum0[4], sum1[4];
#pragma unroll
    for (int q = 0; q < 4; q++) {
        sum0[q] = make_float4(0.f, 0.f, 0.f, 0.f);
        sum1[q] = make_float4(0.f, 0.f, 0.f, 0.f);
    }
    int c0 = 0, c1 = 0;

    for (int r = 0; r < N_REL; r++) {
        if (s_sub[r] == i) {
            c0++;
            const float* row = &g_h_pred[0][(size_t)r * DIM];
#pragma unroll
            for (int q = 0; q < 4; q++) {
                float4 v = *reinterpret_cast<const float4*>(row + q * 1024 + tid * 4);
                sum0[q].x += v.x; sum0[q].y += v.y; sum0[q].z += v.z; sum0[q].w += v.w;
            }
        }
        if (s_obv[r] == i) {
            c1++;
            const float* row = &g_h_pred[1][(size_t)r * DIM];
#pragma unroll
            for (int q = 0; q < 4; q++) {
                float4 v = *reinterpret_cast<const float4*>(row + q * 1024 + tid * 4);
                sum1[q].x += v.x; sum1[q].y += v.y; sum1[q].z += v.z; sum1[q].w += v.w;
            }
        }
    }

    const float inv0 = 1.f / ((float)c0 + EPSF);
    const float inv1 = 1.f / ((float)c1 + EPSF);
    const float invo = 1.f / (255.f + EPSF);
    const float third = 1.f / 3.f;

#pragma unroll
    for (int q = 0; q < 4; q++) {
        int col = q * 1024 + tid * 4;
        float4 h4v = *reinterpret_cast<const float4*>(&g_h_obj[0][(size_t)i * DIM + col]);
        float4 cs  = *reinterpret_cast<const float4*>(&g_colsum4[col]);
        float4 bs  = *reinterpret_cast<const float4*>(&obj_feats[(size_t)i * DIM + col]);
        float4 o;
        o.x = bs.x + ((cs.x - h4v.x) * invo + sum0[q].x * inv0 + sum1[q].x * inv1) * third;
        o.y = bs.y + ((cs.y - h4v.y) * invo + sum0[q].y * inv0 + sum1[q].y * inv1) * third;
        o.z = bs.z + ((cs.z - h4v.z) * invo + sum0[q].z * inv0 + sum1[q].z * inv1) * third;
        o.w = bs.w + ((cs.w - h4v.w) * invo + sum0[q].w * inv0 + sum1[q].w * inv1) * third;
        *reinterpret_cast<float4*>(&out_obj[(size_t)i * DIM + col]) = o;
    }
}

// ---------------- pred side final ----------------
__global__ __launch_bounds__(256)
void pred_final_kernel(const float* __restrict__ pred_feats,
                       const int*   __restrict__ rel_inds,
                       float* __restrict__ out_pred)
{
    __shared__ int s_sub[N_REL];
    __shared__ int s_obv[N_REL];
    const int tid = threadIdx.x;
    for (int t = tid; t < N_REL; t += 256) {
        s_sub[t] = rel_inds[2 * t + 0];
        s_obv[t] = rel_inds[2 * t + 1];
    }
    __syncthreads();

    const int r = blockIdx.x;
    const int my0 = s_sub[r];
    const int my1 = s_obv[r];

    float4 sum5[4];
#pragma unroll
    for (int q = 0; q < 4; q++) sum5[q] = make_float4(0.f, 0.f, 0.f, 0.f);
    int deg = 0;

    for (int j = 0; j < N_REL; j++) {
        if (j == r) continue;
        int a0 = s_sub[j], a1 = s_obv[j];
        bool adj = (a0 == my0) | (a1 == my1) | (a0 == my1) | (a1 == my0);
        if (adj) {
            deg++;
            const float* row = &g_h_pred[2][(size_t)j * DIM];
#pragma unroll
            for (int q = 0; q < 4; q++) {
                float4 v = *reinterpret_cast<const float4*>(row + q * 1024 + tid * 4);
                sum5[q].x += v.x; sum5[q].y += v.y; sum5[q].z += v.z; sum5[q].w += v.w;
            }
        }
    }

    const float invd  = 1.f / ((float)deg + EPSF);
    const float inv1e = 1.f / (1.f + EPSF);
    const float third = 1.f / 3.f;

    const float* h2row = &g_h_obj[1][(size_t)my0 * DIM];
    const float* h3row = &g_h_obj[2][(size_t)my1 * DIM];

#pragma unroll
    for (int q = 0; q < 4; q++) {
        int col = q * 1024 + tid * 4;
        float4 h2v = *reinterpret_cast<const float4*>(h2row + col);
        float4 h3v = *reinterpret_cast<const float4*>(h3row + col);
        float4 bs  = *reinterpret_cast<const float4*>(&pred_feats[(size_t)r * DIM + col]);
        float4 o;
        o.x = bs.x + ((h2v.x + h3v.x) * inv1e + sum5[q].x * invd) * third;
        o.y = bs.y + ((h2v.y + h3v.y) * inv1e + sum5[q].y * invd) * third;
        o.z = bs.z + ((h2v.z + h3v.z) * inv1e + sum5[q].z * invd) * third;
        o.w = bs.w + ((h2v.w + h3v.w) * inv1e + sum5[q].w * invd) * third;
        *reinterpret_cast<float4*>(&out_pred[(size_t)r * DIM + col]) = o;
    }
}

// ---------------- launch ----------------
extern "C" void kernel_launch(void* const* d_in, const int* in_sizes, int n_in,
                              void* d_out, int out_size)
{
    const float* obj_feats  = (const float*)d_in[0];
    const float* pred_feats = (const float*)d_in[1];
    const int*   rel_inds   = (const int*)  d_in[2];
    const float* W_all      = (const float*)d_in[3];
    const float* b_all      = (const float*)d_in[4];

    float* out_obj  = (float*)d_out;
    float* out_pred = (float*)d_out + (size_t)N_OBJ * DIM;

    cudaFuncSetAttribute(gemm_tc, cudaFuncAttributeMaxDynamicSharedMemorySize, SMEM_DYN);

    int n4W = 6 * DIM * DIM / 4;
    conv_w<<<(n4W + 255) / 256, 256>>>((const float4*)W_all, n4W);
    int n4P = N_REL * DIM / 4;
    conv_x<<<(n4P + 255) / 256, 256>>>((const float4*)pred_feats, 0, n4P);
    int n4O = N_OBJ * DIM / 4;
    conv_x<<<(n4O + 255) / 256, 256>>>((const float4*)obj_feats, 1, n4O);

    gemm_tc<<<dim3(30, 32), 256, SMEM_DYN>>>(b_all);

    colsum4_kernel<<<DIM / 256, 256>>>();
    obj_final_kernel<<<N_OBJ, 256>>>(obj_feats, rel_inds, out_obj);
    pred_final_kernel<<<N_REL, 256>>>(pred_feats, rel_inds, out_pred);
}

// round 7
// speedup vs baseline: 4.9787x; 1.4942x over previous
#include <cuda_runtime.h>
#include <cuda_fp16.h>
#include <cstdint>

#define DIM   4096
#define N_OBJ 256
#define N_REL 1024
#define EPSF  1e-7f

// ---------------- scratch (static device arrays; no allocation) ----------------
__device__ float g_h_pred[3][(size_t)N_REL * DIM];
__device__ float g_h_obj[3][(size_t)N_OBJ * DIM];
__device__ float g_colsum4[DIM];
__device__ __half g_Wh[6ull * DIM * DIM];
__device__ __half g_Xph[(size_t)N_REL * DIM];
__device__ __half g_Xoh[(size_t)N_OBJ * DIM];

// ---------------- helpers ----------------
__device__ __forceinline__ uint32_t smem_u32(const void* p) {
    uint32_t a;
    asm("{ .reg .u64 t; cvta.to.shared.u64 t, %1; cvt.u32.u64 %0, t; }"
        : "=r"(a) : "l"(p));
    return a;
}
#define CP16(dst, src) \
    asm volatile("cp.async.cg.shared.global [%0], [%1], 16;" :: "r"(dst), "l"(src) : "memory")
#define LDSM4(r, addr) \
    asm volatile("ldmatrix.sync.aligned.m8n8.x4.shared.b16 {%0,%1,%2,%3}, [%4];" \
        : "=r"((r)[0]), "=r"((r)[1]), "=r"((r)[2]), "=r"((r)[3]) : "r"(addr))

__device__ __forceinline__ void mma16816(float* c, const uint32_t* a,
                                         uint32_t b0, uint32_t b1) {
    asm volatile("mma.sync.aligned.m16n8k16.row.col.f32.f16.f16.f32 "
        "{%0,%1,%2,%3}, {%4,%5,%6,%7}, {%8,%9}, {%0,%1,%2,%3};"
        : "+f"(c[0]), "+f"(c[1]), "+f"(c[2]), "+f"(c[3])
        : "r"(a[0]), "r"(a[1]), "r"(a[2]), "r"(a[3]), "r"(b0), "r"(b1));
}

// ---------------- fp32 -> fp16 (dst resolved IN DEVICE CODE) ----------------
__global__ void conv_h(const float4* __restrict__ src, int which, int n4)
{
    int i = blockIdx.x * blockDim.x + threadIdx.x;
    if (i >= n4) return;
    __half* dst;
    if (which == 0)      dst = g_Wh;
    else if (which == 1) dst = g_Xph;
    else                 dst = g_Xoh;
    float4 v = src[i];
    __half2 h01 = __floats2half2_rn(v.x, v.y);
    __half2 h23 = __floats2half2_rn(v.z, v.w);
    uint2 H;
    H.x = *reinterpret_cast<uint32_t*>(&h01);
    H.y = *reinterpret_cast<uint32_t*>(&h23);
    reinterpret_cast<uint2*>(dst)[i] = H;
}

// ---------------- tensor-core GEMM: H = relu(X @ W^T + b) ----------------
// CTA tile 128x128, k-chunk 32 fp16. 8 warps, warp tile 64x32.
// 2 smem tiles (Xh, Wh), pitch 80 B/row, double-buffered, 1 barrier/chunk.
#define KC        32
#define PITCH     80
#define TILEB     (128 * PITCH)       // 10240 B per tile
#define BUFB      (2 * TILEB)         // Xh, Wh
#define SMEM_DYN  (2 * BUFB)          // 40960 B

__global__ __launch_bounds__(256, 2)
void gemm_tc(const float* __restrict__ b_all)
{
    extern __shared__ char sm_raw[];
    const uint32_t tiles = smem_u32(sm_raw);

    const int tid  = threadIdx.x;
    const int wid  = tid >> 5;
    const int lane = tid & 31;
    const uint32_t lrow = lane & 15;
    const uint32_t lsel = lane >> 4;
    const int wm = (wid >> 2) * 64;    // 0 or 64
    const int wn = (wid & 3) * 32;     // 0..96

    const int slot = blockIdx.x;
    const int bn   = blockIdx.y * 128;
    int bm, widx;
    const __half* Ah;
    float* H;
    if (slot < 24) {
        int z = slot >> 3; bm = (slot & 7) * 128;
        Ah = g_Xph; H = &g_h_pred[z][0];
        widx = (z == 2) ? 5 : z;
    } else {
        int s = slot - 24; int z = s >> 1; bm = (s & 1) * 128;
        Ah = g_Xoh; H = &g_h_obj[z][0];
        widx = (z == 0) ? 4 : (z + 1);
    }
    const char* gbase[2];
    gbase[0] = (const char*)Ah + (size_t)bm * (DIM * 2);
    gbase[1] = (const char*)(g_Wh + (size_t)widx * DIM * DIM) + (size_t)bn * (DIM * 2);
    const float* bias = b_all + (size_t)widx * DIM + bn;

    float c[4][4][4];
#pragma unroll
    for (int i = 0; i < 4; i++)
#pragma unroll
        for (int j = 0; j < 4; j++)
#pragma unroll
            for (int q = 0; q < 4; q++) c[i][j][q] = 0.f;

    const int NC = DIM / KC;   // 128 chunks
    const int r_ld = tid >> 2, u_ld = tid & 3;

    // ---- preload chunk 0 ----
#pragma unroll
    for (int t = 0; t < 2; t++) {
        CP16(tiles + t * TILEB + r_ld * PITCH + u_ld * 16,
             gbase[t] + (size_t)r_ld * (DIM * 2) + u_ld * 16);
        CP16(tiles + t * TILEB + (r_ld + 64) * PITCH + u_ld * 16,
             gbase[t] + (size_t)(r_ld + 64) * (DIM * 2) + u_ld * 16);
    }
    asm volatile("cp.async.commit_group;" ::: "memory");

    for (int kc = 0; kc < NC; kc++) {
        asm volatile("cp.async.wait_group 0;" ::: "memory");
        __syncthreads();

        if (kc + 1 < NC) {
            uint32_t dstb = tiles + ((kc + 1) & 1) * BUFB;
            size_t koff = (size_t)(kc + 1) * (KC * 2);
#pragma unroll
            for (int t = 0; t < 2; t++) {
                CP16(dstb + t * TILEB + r_ld * PITCH + u_ld * 16,
                     gbase[t] + (size_t)r_ld * (DIM * 2) + koff + u_ld * 16);
                CP16(dstb + t * TILEB + (r_ld + 64) * PITCH + u_ld * 16,
                     gbase[t] + (size_t)(r_ld + 64) * (DIM * 2) + koff + u_ld * 16);
            }
            asm volatile("cp.async.commit_group;" ::: "memory");
        }

        const uint32_t bufb = tiles + (kc & 1) * BUFB;
#pragma unroll
        for (int ks = 0; ks < 2; ks++) {
            const uint32_t uoff = (ks * 2 + lsel) * 16;
            uint32_t bh[2][4];
#pragma unroll
            for (int jj = 0; jj < 2; jj++) {
                uint32_t rb = bufb + TILEB + (wn + 16 * jj + lrow) * PITCH + uoff;
                LDSM4(bh[jj], rb);
            }
            uint32_t ah[4][4];
#pragma unroll
            for (int i = 0; i < 4; i++) {
                uint32_t ra = bufb + (wm + 16 * i + lrow) * PITCH + uoff;
                LDSM4(ah[i], ra);
            }
#pragma unroll
            for (int i = 0; i < 4; i++)
#pragma unroll
                for (int j = 0; j < 4; j++) {
                    const int jj = j >> 1, jo = j & 1;
                    mma16816(c[i][j], ah[i], bh[jj][jo], bh[jj][jo + 2]);
                }
        }
    }

    // ---- epilogue: bias + relu, direct stores ----
    const int qrow = lane >> 2;          // 0..7
    const int qcol = (lane & 3) * 2;     // 0,2,4,6
#pragma unroll
    for (int i = 0; i < 4; i++) {
        int grow0 = bm + wm + 16 * i + qrow;
#pragma unroll
        for (int j = 0; j < 4; j++) {
            int gcol = bn + wn + 8 * j + qcol;
            float b0 = bias[wn + 8 * j + qcol];
            float b1 = bias[wn + 8 * j + qcol + 1];
            float2 v0, v1;
            v0.x = fmaxf(c[i][j][0] + b0, 0.f);
            v0.y = fmaxf(c[i][j][1] + b1, 0.f);
            v1.x = fmaxf(c[i][j][2] + b0, 0.f);
            v1.y = fmaxf(c[i][j][3] + b1, 0.f);
            *reinterpret_cast<float2*>(H + (size_t)grow0 * DIM + gcol) = v0;
            *reinterpret_cast<float2*>(H + (size_t)(grow0 + 8) * DIM + gcol) = v1;
        }
    }
}

// ---------------- column sums of h4 ----------------
__global__ void colsum4_kernel()
{
    int c = blockIdx.x * blockDim.x + threadIdx.x;
    float s = 0.f;
    for (int r = 0; r < N_OBJ; r++) s += g_h_obj[0][(size_t)r * DIM + c];
    g_colsum4[c] = s;
}

// ---------------- obj side final ----------------
__global__ __launch_bounds__(256)
void obj_final_kernel(const float* __restrict__ obj_feats,
                      const int*   __restrict__ rel_inds,
                      float* __restrict__ out_obj)
{
    __shared__ int s_sub[N_REL];
    __shared__ int s_obv[N_REL];
    const int tid = threadIdx.x;
    for (int t = tid; t < N_REL; t += 256) {
        s_sub[t] = rel_inds[2 * t + 0];
        s_obv[t] = rel_inds[2 * t + 1];
    }
    __syncthreads();

    const int i = blockIdx.x;
    float4 sum0[4], sum1[4];
#pragma unroll
    for (int q = 0; q < 4; q++) {
        sum0[q] = make_float4(0.f, 0.f, 0.f, 0.f);
        sum1[q] = make_float4(0.f, 0.f, 0.f, 0.f);
    }
    int c0 = 0, c1 = 0;

    for (int r = 0; r < N_REL; r++) {
        if (s_sub[r] == i) {
            c0++;
            const float* row = &g_h_pred[0][(size_t)r * DIM];
#pragma unroll
            for (int q = 0; q < 4; q++) {
                float4 v = *reinterpret_cast<const float4*>(row + q * 1024 + tid * 4);
                sum0[q].x += v.x; sum0[q].y += v.y; sum0[q].z += v.z; sum0[q].w += v.w;
            }
        }
        if (s_obv[r] == i) {
            c1++;
            const float* row = &g_h_pred[1][(size_t)r * DIM];
#pragma unroll
            for (int q = 0; q < 4; q++) {
                float4 v = *reinterpret_cast<const float4*>(row + q * 1024 + tid * 4);
                sum1[q].x += v.x; sum1[q].y += v.y; sum1[q].z += v.z; sum1[q].w += v.w;
            }
        }
    }

    const float inv0 = 1.f / ((float)c0 + EPSF);
    const float inv1 = 1.f / ((float)c1 + EPSF);
    const float invo = 1.f / (255.f + EPSF);
    const float third = 1.f / 3.f;

#pragma unroll
    for (int q = 0; q < 4; q++) {
        int col = q * 1024 + tid * 4;
        float4 h4v = *reinterpret_cast<const float4*>(&g_h_obj[0][(size_t)i * DIM + col]);
        float4 cs  = *reinterpret_cast<const float4*>(&g_colsum4[col]);
        float4 bs  = *reinterpret_cast<const float4*>(&obj_feats[(size_t)i * DIM + col]);
        float4 o;
        o.x = bs.x + ((cs.x - h4v.x) * invo + sum0[q].x * inv0 + sum1[q].x * inv1) * third;
        o.y = bs.y + ((cs.y - h4v.y) * invo + sum0[q].y * inv0 + sum1[q].y * inv1) * third;
        o.z = bs.z + ((cs.z - h4v.z) * invo + sum0[q].z * inv0 + sum1[q].z * inv1) * third;
        o.w = bs.w + ((cs.w - h4v.w) * invo + sum0[q].w * inv0 + sum1[q].w * inv1) * third;
        *reinterpret_cast<float4*>(&out_obj[(size_t)i * DIM + col]) = o;
    }
}

// ---------------- pred side final ----------------
__global__ __launch_bounds__(256)
void pred_final_kernel(const float* __restrict__ pred_feats,
                       const int*   __restrict__ rel_inds,
                       float* __restrict__ out_pred)
{
    __shared__ int s_sub[N_REL];
    __shared__ int s_obv[N_REL];
    const int tid = threadIdx.x;
    for (int t = tid; t < N_REL; t += 256) {
        s_sub[t] = rel_inds[2 * t + 0];
        s_obv[t] = rel_inds[2 * t + 1];
    }
    __syncthreads();

    const int r = blockIdx.x;
    const int my0 = s_sub[r];
    const int my1 = s_obv[r];

    float4 sum5[4];
#pragma unroll
    for (int q = 0; q < 4; q++) sum5[q] = make_float4(0.f, 0.f, 0.f, 0.f);
    int deg = 0;

    for (int j = 0; j < N_REL; j++) {
        if (j == r) continue;
        int a0 = s_sub[j], a1 = s_obv[j];
        bool adj = (a0 == my0) | (a1 == my1) | (a0 == my1) | (a1 == my0);
        if (adj) {
            deg++;
            const float* row = &g_h_pred[2][(size_t)j * DIM];
#pragma unroll
            for (int q = 0; q < 4; q++) {
                float4 v = *reinterpret_cast<const float4*>(row + q * 1024 + tid * 4);
                sum5[q].x += v.x; sum5[q].y += v.y; sum5[q].z += v.z; sum5[q].w += v.w;
            }
        }
    }

    const float invd  = 1.f / ((float)deg + EPSF);
    const float inv1e = 1.f / (1.f + EPSF);
    const float third = 1.f / 3.f;

    const float* h2row = &g_h_obj[1][(size_t)my0 * DIM];
    const float* h3row = &g_h_obj[2][(size_t)my1 * DIM];

#pragma unroll
    for (int q = 0; q < 4; q++) {
        int col = q * 1024 + tid * 4;
        float4 h2v = *reinterpret_cast<const float4*>(h2row + col);
        float4 h3v = *reinterpret_cast<const float4*>(h3row + col);
        float4 bs  = *reinterpret_cast<const float4*>(&pred_feats[(size_t)r * DIM + col]);
        float4 o;
        o.x = bs.x + ((h2v.x + h3v.x) * inv1e + sum5[q].x * invd) * third;
        o.y = bs.y + ((h2v.y + h3v.y) * inv1e + sum5[q].y * invd) * third;
        o.z = bs.z + ((h2v.z + h3v.z) * inv1e + sum5[q].z * invd) * third;
        o.w = bs.w + ((h2v.w + h3v.w) * inv1e + sum5[q].w * invd) * third;
        *reinterpret_cast<float4*>(&out_pred[(size_t)r * DIM + col]) = o;
    }
}

// ---------------- launch ----------------
extern "C" void kernel_launch(void* const* d_in, const int* in_sizes, int n_in,
                              void* d_out, int out_size)
{
    const float* obj_feats  = (const float*)d_in[0];
    const float* pred_feats = (const float*)d_in[1];
    const int*   rel_inds   = (const int*)  d_in[2];
    const float* W_all      = (const float*)d_in[3];
    const float* b_all      = (const float*)d_in[4];

    float* out_obj  = (float*)d_out;
    float* out_pred = (float*)d_out + (size_t)N_OBJ * DIM;

    cudaFuncSetAttribute(gemm_tc, cudaFuncAttributeMaxDynamicSharedMemorySize, SMEM_DYN);

    int n4W = 6 * DIM * DIM / 4;
    conv_h<<<(n4W + 255) / 256, 256>>>((const float4*)W_all, 0, n4W);
    int n4P = N_REL * DIM / 4;
    conv_h<<<(n4P + 255) / 256, 256>>>((const float4*)pred_feats, 1, n4P);
    int n4O = N_OBJ * DIM / 4;
    conv_h<<<(n4O + 255) / 256, 256>>>((const float4*)obj_feats, 2, n4O);

    gemm_tc<<<dim3(30, 32), 256, SMEM_DYN>>>(b_all);

    colsum4_kernel<<<DIM / 256, 256>>>();
    obj_final_kernel<<<N_OBJ, 256>>>(obj_feats, rel_inds, out_obj);
    pred_final_kernel<<<N_REL, 256>>>(pred_feats, rel_inds, out_pred);
}

// round 8
// speedup vs baseline: 6.1450x; 1.2343x over previous
#include <cuda_runtime.h>
#include <cuda_fp16.h>
#include <cstdint>

#define DIM   4096
#define N_OBJ 256
#define N_REL 1024
#define EPSF  1e-7f
#define ADJ_MAX 96
#define SUB_MAX 48

// ---------------- scratch (static device arrays; no allocation) ----------------
__device__ float g_h_pred[3][(size_t)N_REL * DIM];
__device__ float g_h_obj[3][(size_t)N_OBJ * DIM];
__device__ float g_colsum4[DIM];
__device__ float g_cspart[8][DIM];
__device__ __half g_Wh[6ull * DIM * DIM];
__device__ __half g_Xph[(size_t)N_REL * DIM];
__device__ __half g_Xoh[(size_t)N_OBJ * DIM];
__device__ int g_adj[N_REL * ADJ_MAX];
__device__ int g_adj_cnt[N_REL];
__device__ int g_sub_list[N_OBJ * SUB_MAX];
__device__ int g_sub_cnt[N_OBJ];
__device__ int g_obv_list[N_OBJ * SUB_MAX];
__device__ int g_obv_cnt[N_OBJ];

// ---------------- helpers ----------------
__device__ __forceinline__ uint32_t smem_u32(const void* p) {
    uint32_t a;
    asm("{ .reg .u64 t; cvta.to.shared.u64 t, %1; cvt.u32.u64 %0, t; }"
        : "=r"(a) : "l"(p));
    return a;
}
#define CP16(dst, src) \
    asm volatile("cp.async.cg.shared.global [%0], [%1], 16;" :: "r"(dst), "l"(src) : "memory")
#define LDSM4(r, addr) \
    asm volatile("ldmatrix.sync.aligned.m8n8.x4.shared.b16 {%0,%1,%2,%3}, [%4];" \
        : "=r"((r)[0]), "=r"((r)[1]), "=r"((r)[2]), "=r"((r)[3]) : "r"(addr))

__device__ __forceinline__ void mma16816(float* c, const uint32_t* a,
                                         uint32_t b0, uint32_t b1) {
    asm volatile("mma.sync.aligned.m16n8k16.row.col.f32.f16.f16.f32 "
        "{%0,%1,%2,%3}, {%4,%5,%6,%7}, {%8,%9}, {%0,%1,%2,%3};"
        : "+f"(c[0]), "+f"(c[1]), "+f"(c[2]), "+f"(c[3])
        : "r"(a[0]), "r"(a[1]), "r"(a[2]), "r"(a[3]), "r"(b0), "r"(b1));
}

// ---------------- fp32 -> fp16 (dst resolved IN DEVICE CODE) ----------------
__global__ void conv_h(const float4* __restrict__ src, int which, int n4)
{
    int i = blockIdx.x * blockDim.x + threadIdx.x;
    if (i >= n4) return;
    __half* dst;
    if (which == 0)      dst = g_Wh;
    else if (which == 1) dst = g_Xph;
    else                 dst = g_Xoh;
    float4 v = src[i];
    __half2 h01 = __floats2half2_rn(v.x, v.y);
    __half2 h23 = __floats2half2_rn(v.z, v.w);
    uint2 H;
    H.x = *reinterpret_cast<uint32_t*>(&h01);
    H.y = *reinterpret_cast<uint32_t*>(&h23);
    reinterpret_cast<uint2*>(dst)[i] = H;
}

// ---------------- deterministic adjacency-list build (1 warp / rel) ----------------
__global__ void build_adj(const int* __restrict__ rel_inds)
{
    const int r = blockIdx.x;
    const int lane = threadIdx.x;
    const int my0 = rel_inds[2 * r], my1 = rel_inds[2 * r + 1];
    int base = 0;
    for (int it = 0; it < N_REL / 32; it++) {
        int j = it * 32 + lane;
        int a0 = rel_inds[2 * j], a1 = rel_inds[2 * j + 1];
        bool adj = (j != r) &&
                   ((a0 == my0) | (a1 == my1) | (a0 == my1) | (a1 == my0));
        unsigned m = __ballot_sync(0xffffffffu, adj);
        if (adj) {
            int pos = base + __popc(m & ((1u << lane) - 1u));
            if (pos < ADJ_MAX) g_adj[r * ADJ_MAX + pos] = j;
        }
        base += __popc(m);
    }
    if (lane == 0) g_adj_cnt[r] = (base < ADJ_MAX) ? base : ADJ_MAX;
}

// ---------------- deterministic subj/obj lists (1 warp / object) ----------------
__global__ void build_obj_lists(const int* __restrict__ rel_inds)
{
    const int i = blockIdx.x;
    const int lane = threadIdx.x;
    int b0 = 0, b1 = 0;
    for (int it = 0; it < N_REL / 32; it++) {
        int r = it * 32 + lane;
        int s = rel_inds[2 * r], o = rel_inds[2 * r + 1];
        bool f0 = (s == i);
        unsigned m0 = __ballot_sync(0xffffffffu, f0);
        if (f0) {
            int pos = b0 + __popc(m0 & ((1u << lane) - 1u));
            if (pos < SUB_MAX) g_sub_list[i * SUB_MAX + pos] = r;
        }
        b0 += __popc(m0);
        bool f1 = (o == i);
        unsigned m1 = __ballot_sync(0xffffffffu, f1);
        if (f1) {
            int pos = b1 + __popc(m1 & ((1u << lane) - 1u));
            if (pos < SUB_MAX) g_obv_list[i * SUB_MAX + pos] = r;
        }
        b1 += __popc(m1);
    }
    if (lane == 0) {
        g_sub_cnt[i] = (b0 < SUB_MAX) ? b0 : SUB_MAX;
        g_obv_cnt[i] = (b1 < SUB_MAX) ? b1 : SUB_MAX;
    }
}

// ---------------- tensor-core GEMM: H = relu(X @ W^T + b) ----------------
#define KC        32
#define PITCH     80
#define TILEB     (128 * PITCH)
#define BUFB      (2 * TILEB)
#define SMEM_DYN  (2 * BUFB)          // 40960 B

__global__ __launch_bounds__(256, 2)
void gemm_tc(const float* __restrict__ b_all)
{
    extern __shared__ char sm_raw[];
    const uint32_t tiles = smem_u32(sm_raw);

    const int tid  = threadIdx.x;
    const int wid  = tid >> 5;
    const int lane = tid & 31;
    const uint32_t lrow = lane & 15;
    const uint32_t lsel = lane >> 4;
    const int wm = (wid >> 2) * 64;
    const int wn = (wid & 3) * 32;

    const int slot = blockIdx.x;
    const int bn   = blockIdx.y * 128;
    int bm, widx;
    const __half* Ah;
    float* H;
    if (slot < 24) {
        int z = slot >> 3; bm = (slot & 7) * 128;
        Ah = g_Xph; H = &g_h_pred[z][0];
        widx = (z == 2) ? 5 : z;
    } else {
        int s = slot - 24; int z = s >> 1; bm = (s & 1) * 128;
        Ah = g_Xoh; H = &g_h_obj[z][0];
        widx = (z == 0) ? 4 : (z + 1);
    }
    const char* gbase[2];
    gbase[0] = (const char*)Ah + (size_t)bm * (DIM * 2);
    gbase[1] = (const char*)(g_Wh + (size_t)widx * DIM * DIM) + (size_t)bn * (DIM * 2);
    const float* bias = b_all + (size_t)widx * DIM + bn;

    float c[4][4][4];
#pragma unroll
    for (int i = 0; i < 4; i++)
#pragma unroll
        for (int j = 0; j < 4; j++)
#pragma unroll
            for (int q = 0; q < 4; q++) c[i][j][q] = 0.f;

    const int NC = DIM / KC;
    const int r_ld = tid >> 2, u_ld = tid & 3;

#pragma unroll
    for (int t = 0; t < 2; t++) {
        CP16(tiles + t * TILEB + r_ld * PITCH + u_ld * 16,
             gbase[t] + (size_t)r_ld * (DIM * 2) + u_ld * 16);
        CP16(tiles + t * TILEB + (r_ld + 64) * PITCH + u_ld * 16,
             gbase[t] + (size_t)(r_ld + 64) * (DIM * 2) + u_ld * 16);
    }
    asm volatile("cp.async.commit_group;" ::: "memory");

    for (int kc = 0; kc < NC; kc++) {
        asm volatile("cp.async.wait_group 0;" ::: "memory");
        __syncthreads();

        if (kc + 1 < NC) {
            uint32_t dstb = tiles + ((kc + 1) & 1) * BUFB;
            size_t koff = (size_t)(kc + 1) * (KC * 2);
#pragma unroll
            for (int t = 0; t < 2; t++) {
                CP16(dstb + t * TILEB + r_ld * PITCH + u_ld * 16,
                     gbase[t] + (size_t)r_ld * (DIM * 2) + koff + u_ld * 16);
                CP16(dstb + t * TILEB + (r_ld + 64) * PITCH + u_ld * 16,
                     gbase[t] + (size_t)(r_ld + 64) * (DIM * 2) + koff + u_ld * 16);
            }
            asm volatile("cp.async.commit_group;" ::: "memory");
        }

        const uint32_t bufb = tiles + (kc & 1) * BUFB;
#pragma unroll
        for (int ks = 0; ks < 2; ks++) {
            const uint32_t uoff = (ks * 2 + lsel) * 16;
            uint32_t bh[2][4];
#pragma unroll
            for (int jj = 0; jj < 2; jj++) {
                uint32_t rb = bufb + TILEB + (wn + 16 * jj + lrow) * PITCH + uoff;
                LDSM4(bh[jj], rb);
            }
            uint32_t ah[4][4];
#pragma unroll
            for (int i = 0; i < 4; i++) {
                uint32_t ra = bufb + (wm + 16 * i + lrow) * PITCH + uoff;
                LDSM4(ah[i], ra);
            }
#pragma unroll
            for (int i = 0; i < 4; i++)
#pragma unroll
                for (int j = 0; j < 4; j++) {
                    const int jj = j >> 1, jo = j & 1;
                    mma16816(c[i][j], ah[i], bh[jj][jo], bh[jj][jo + 2]);
                }
        }
    }

    const int qrow = lane >> 2;
    const int qcol = (lane & 3) * 2;
#pragma unroll
    for (int i = 0; i < 4; i++) {
        int grow0 = bm + wm + 16 * i + qrow;
#pragma unroll
        for (int j = 0; j < 4; j++) {
            int gcol = bn + wn + 8 * j + qcol;
            float b0 = bias[wn + 8 * j + qcol];
            float b1 = bias[wn + 8 * j + qcol + 1];
            float2 v0, v1;
            v0.x = fmaxf(c[i][j][0] + b0, 0.f);
            v0.y = fmaxf(c[i][j][1] + b1, 0.f);
            v1.x = fmaxf(c[i][j][2] + b0, 0.f);
            v1.y = fmaxf(c[i][j][3] + b1, 0.f);
            *reinterpret_cast<float2*>(H + (size_t)grow0 * DIM + gcol) = v0;
            *reinterpret_cast<float2*>(H + (size_t)(grow0 + 8) * DIM + gcol) = v1;
        }
    }
}

// ---------------- column sums of h4 (two-stage, deterministic) ----------------
__global__ void colsum_part()
{
    int c = blockIdx.x * blockDim.x + threadIdx.x;
    int z = blockIdx.y;
    float s = 0.f;
    for (int r = z * 32; r < z * 32 + 32; r++)
        s += g_h_obj[0][(size_t)r * DIM + c];
    g_cspart[z][c] = s;
}
__global__ void colsum_red()
{
    int c = blockIdx.x * blockDim.x + threadIdx.x;
    float s = 0.f;
#pragma unroll
    for (int z = 0; z < 8; z++) s += g_cspart[z][c];
    g_colsum4[c] = s;
}

// ---------------- obj side final (list gather, 4 col-segments) ----------------
__global__ __launch_bounds__(256)
void obj_final_kernel(const float* __restrict__ obj_feats,
                      float* __restrict__ out_obj)
{
    const int i   = blockIdx.y;
    const int col = blockIdx.x * 1024 + threadIdx.x * 4;

    const int c0 = g_sub_cnt[i];
    const int c1 = g_obv_cnt[i];

    float4 sum0 = make_float4(0.f, 0.f, 0.f, 0.f);
    float4 sum1 = make_float4(0.f, 0.f, 0.f, 0.f);
    for (int k = 0; k < c0; k++) {
        int r = g_sub_list[i * SUB_MAX + k];
        float4 v = *reinterpret_cast<const float4*>(&g_h_pred[0][(size_t)r * DIM + col]);
        sum0.x += v.x; sum0.y += v.y; sum0.z += v.z; sum0.w += v.w;
    }
    for (int k = 0; k < c1; k++) {
        int r = g_obv_list[i * SUB_MAX + k];
        float4 v = *reinterpret_cast<const float4*>(&g_h_pred[1][(size_t)r * DIM + col]);
        sum1.x += v.x; sum1.y += v.y; sum1.z += v.z; sum1.w += v.w;
    }

    const float inv0 = 1.f / ((float)c0 + EPSF);
    const float inv1 = 1.f / ((float)c1 + EPSF);
    const float invo = 1.f / (255.f + EPSF);
    const float third = 1.f / 3.f;

    float4 h4v = *reinterpret_cast<const float4*>(&g_h_obj[0][(size_t)i * DIM + col]);
    float4 cs  = *reinterpret_cast<const float4*>(&g_colsum4[col]);
    float4 bs  = *reinterpret_cast<const float4*>(&obj_feats[(size_t)i * DIM + col]);
    float4 o;
    o.x = bs.x + ((cs.x - h4v.x) * invo + sum0.x * inv0 + sum1.x * inv1) * third;
    o.y = bs.y + ((cs.y - h4v.y) * invo + sum0.y * inv0 + sum1.y * inv1) * third;
    o.z = bs.z + ((cs.z - h4v.z) * invo + sum0.z * inv0 + sum1.z * inv1) * third;
    o.w = bs.w + ((cs.w - h4v.w) * invo + sum0.w * inv0 + sum1.w * inv1) * third;
    *reinterpret_cast<float4*>(&out_obj[(size_t)i * DIM + col]) = o;
}

// ---------------- pred side final (adjacency gather, 4 col-segments) ----------------
__global__ __launch_bounds__(256)
void pred_final_kernel(const float* __restrict__ pred_feats,
                       const int*   __restrict__ rel_inds,
                       float* __restrict__ out_pred)
{
    const int r   = blockIdx.y;
    const int col = blockIdx.x * 1024 + threadIdx.x * 4;

    const int my0 = rel_inds[2 * r];
    const int my1 = rel_inds[2 * r + 1];
    const int deg = g_adj_cnt[r];

    float4 sum5 = make_float4(0.f, 0.f, 0.f, 0.f);
    for (int k = 0; k < deg; k++) {
        int j = g_adj[r * ADJ_MAX + k];
        float4 v = *reinterpret_cast<const float4*>(&g_h_pred[2][(size_t)j * DIM + col]);
        sum5.x += v.x; sum5.y += v.y; sum5.z += v.z; sum5.w += v.w;
    }

    const float invd  = 1.f / ((float)deg + EPSF);
    const float inv1e = 1.f / (1.f + EPSF);
    const float third = 1.f / 3.f;

    float4 h2v = *reinterpret_cast<const float4*>(&g_h_obj[1][(size_t)my0 * DIM + col]);
    float4 h3v = *reinterpret_cast<const float4*>(&g_h_obj[2][(size_t)my1 * DIM + col]);
    float4 bs  = *reinterpret_cast<const float4*>(&pred_feats[(size_t)r * DIM + col]);
    float4 o;
    o.x = bs.x + ((h2v.x + h3v.x) * inv1e + sum5.x * invd) * third;
    o.y = bs.y + ((h2v.y + h3v.y) * inv1e + sum5.y * invd) * third;
    o.z = bs.z + ((h2v.z + h3v.z) * inv1e + sum5.z * invd) * third;
    o.w = bs.w + ((h2v.w + h3v.w) * inv1e + sum5.w * invd) * third;
    *reinterpret_cast<float4*>(&out_pred[(size_t)r * DIM + col]) = o;
}

// ---------------- launch ----------------
extern "C" void kernel_launch(void* const* d_in, const int* in_sizes, int n_in,
                              void* d_out, int out_size)
{
    const float* obj_feats  = (const float*)d_in[0];
    const float* pred_feats = (const float*)d_in[1];
    const int*   rel_inds   = (const int*)  d_in[2];
    const float* W_all      = (const float*)d_in[3];
    const float* b_all      = (const float*)d_in[4];

    float* out_obj  = (float*)d_out;
    float* out_pred = (float*)d_out + (size_t)N_OBJ * DIM;

    cudaFuncSetAttribute(gemm_tc, cudaFuncAttributeMaxDynamicSharedMemorySize, SMEM_DYN);

    int n4W = 6 * DIM * DIM / 4;
    conv_h<<<(n4W + 255) / 256, 256>>>((const float4*)W_all, 0, n4W);
    int n4P = N_REL * DIM / 4;
    conv_h<<<(n4P + 255) / 256, 256>>>((const float4*)pred_feats, 1, n4P);
    int n4O = N_OBJ * DIM / 4;
    conv_h<<<(n4O + 255) / 256, 256>>>((const float4*)obj_feats, 2, n4O);

    build_adj<<<N_REL, 32>>>(rel_inds);
    build_obj_lists<<<N_OBJ, 32>>>(rel_inds);

    gemm_tc<<<dim3(30, 32), 256, SMEM_DYN>>>(b_all);

    colsum_part<<<dim3(DIM / 256, 8), 256>>>();
    colsum_red<<<DIM / 256, 256>>>();

    obj_final_kernel<<<dim3(4, N_OBJ), 256>>>(obj_feats, out_obj);
    pred_final_kernel<<<dim3(4, N_REL), 256>>>(pred_feats, rel_inds, out_pred);
}